// round 2
// baseline (speedup 1.0000x reference)
#include <cuda_runtime.h>
#include <cstdint>

// ---------------- problem constants ----------------
#define B_SIZE 4096
#define C_CH   22
#define T_FULL 1002      // x row stride (last sample is subject id)
#define T_IN   1001
#define K_OUT  40
#define KSZ    25
#define W_OUT  977       // T_IN - KSZ + 1
#define P_POOL 100
#define N_POOL 9
#define FEAT   360       // K_OUT * N_POOL
#define O_OUT  4

// ---------------- tiling ----------------
#define WT     8                  // w positions per thread tile
#define NWT    123                // ceil(977/8) -> covers 984 (tail masked)
#define KT     10                 // k per thread tile (5 f32x2 pairs)
#define NKT    4                  // 40/10
#define NTILES (NWT*NKT)          // 492
#define XROW   1008               // padded x row in smem (16B aligned, covers w<=983+24)
#define SX_ELEMS (C_CH*XROW)          // 22176
#define SW_ELEMS (C_CH*KSZ*K_OUT)     // 22000
#define SMEM_BYTES ((SX_ELEMS + SW_ELEMS + FEAT + 2*K_OUT) * 4)  // 178464

// ---------------- device scratch (no allocations allowed) ----------------
__device__ float g_wt[SW_ELEMS];                       // weights transposed to [c][t][k]
__device__ float g_pooled[(size_t)B_SIZE * FEAT];      // pooled ELU outputs (pre-BN)
__device__ float g_bnpart[(size_t)B_SIZE * 2 * K_OUT]; // per-CTA sum / sumsq
__device__ float g_scale[K_OUT];
__device__ float g_shift[K_OUT];

// ---------------- f32x2 helpers (sm_103a packed fp32) ----------------
__device__ __forceinline__ unsigned long long pack2(float v) {
    unsigned long long r;
    unsigned int u = __float_as_uint(v);
    asm("mov.b64 %0, {%1, %1};" : "=l"(r) : "r"(u));
    return r;
}
__device__ __forceinline__ void fma2(unsigned long long& d,
                                     unsigned long long a,
                                     unsigned long long b) {
    asm("fma.rn.f32x2 %0, %1, %2, %0;" : "+l"(d) : "l"(a), "l"(b));
}
__device__ __forceinline__ void unpack2(unsigned long long v, float& lo, float& hi) {
    unsigned int l, h;
    asm("mov.b64 {%0, %1}, %2;" : "=r"(l), "=r"(h) : "l"(v));
    lo = __uint_as_float(l);
    hi = __uint_as_float(h);
}

// ---------------- pass 0: transpose weights to [c][t][k] (k contiguous) ----------------
__global__ void transpose_w_kernel(const float* __restrict__ cw) {
    int i = blockIdx.x * blockDim.x + threadIdx.x;
    if (i >= SW_ELEMS) return;
    int k = i / (C_CH * KSZ);
    int r = i - k * (C_CH * KSZ);
    int c = r / KSZ;
    int t = r - c * KSZ;
    g_wt[(c * KSZ + t) * K_OUT + k] = cw[i];
}

// ---------------- pass 1: conv + bias + ELU + pool + BN partials ----------------
__global__ void __launch_bounds__(256, 1)
conv_kernel(const float* __restrict__ x, const float* __restrict__ bias) {
    extern __shared__ float smem[];
    float* sx    = smem;                    // [22][1008]
    float* sw    = sx + SX_ELEMS;           // [22][25][40]
    float* spool = sw + SW_ELEMS;           // [40][9]
    float* sb1   = spool + FEAT;            // [40]
    float* sb2   = sb1 + K_OUT;             // [40]

    const int tid = threadIdx.x;
    const int b   = blockIdx.x;

    const float* xg = x + (size_t)b * (C_CH * T_FULL);
    for (int i = tid; i < SX_ELEMS; i += 256) {
        int c = i / XROW;
        int w = i - c * XROW;
        sx[i] = (w < T_IN) ? xg[c * T_FULL + w] : 0.0f;
    }
    for (int i = tid; i < SW_ELEMS; i += 256) sw[i] = g_wt[i];
    for (int i = tid; i < FEAT + 2 * K_OUT; i += 256) spool[i] = 0.0f;
    __syncthreads();

    const int kt = tid & 3;       // stable across idx += 256 strides (256 % 4 == 0)
    const int k0 = kt * KT;

    float s1k[KT], s2k[KT];
#pragma unroll
    for (int i = 0; i < KT; i++) { s1k[i] = 0.0f; s2k[i] = 0.0f; }

    for (int idx = tid; idx < NTILES; idx += 256) {
        const int w0 = (idx >> 2) * WT;

        unsigned long long acc[5][WT];
#pragma unroll
        for (int p = 0; p < 5; p++)
#pragma unroll
            for (int j = 0; j < WT; j++) acc[p][j] = 0ull;

        for (int c = 0; c < C_CH; ++c) {
            // 32-float sliding window for this channel, vectorized LDS.128
            const float4* xr4 = (const float4*)(sx + c * XROW + w0);
            float xs[32];
#pragma unroll
            for (int q = 0; q < 8; q++) {
                float4 v = xr4[q];
                xs[4*q+0] = v.x; xs[4*q+1] = v.y; xs[4*q+2] = v.z; xs[4*q+3] = v.w;
            }
            const float* wr = sw + c * (KSZ * K_OUT) + k0;
#pragma unroll
            for (int t = 0; t < KSZ; t++) {
                unsigned long long wp[5];
#pragma unroll
                for (int p = 0; p < 5; p++)
                    wp[p] = *(const unsigned long long*)(wr + t * K_OUT + 2 * p);  // LDS.64 (k,k+1)
#pragma unroll
                for (int j = 0; j < WT; j++) {
                    unsigned long long xp = pack2(xs[t + j]);
#pragma unroll
                    for (int p = 0; p < 5; p++) fma2(acc[p][j], wp[p], xp);
                }
            }
        }

        // epilogue: bias + ELU + masked BN stats + masked pooling
        const int pool0 = w0 / P_POOL;
        const int bnd   = (pool0 + 1) * P_POOL;
#pragma unroll
        for (int p = 0; p < 5; p++) {
            const int ka = k0 + 2 * p;
            const int kb = ka + 1;
            const float ba = bias[ka];
            const float bb = bias[kb];
            float pa[2] = {0.0f, 0.0f};
            float pb[2] = {0.0f, 0.0f};
#pragma unroll
            for (int j = 0; j < WT; j++) {
                float va, vb;
                unpack2(acc[p][j], va, vb);
                va += ba; vb += bb;
                float ya = va > 0.0f ? va : (__expf(va) - 1.0f);
                float yb = vb > 0.0f ? vb : (__expf(vb) - 1.0f);
                int w = w0 + j;
                if (w < W_OUT) {
                    s1k[2*p]   += ya;  s2k[2*p]   += ya * ya;
                    s1k[2*p+1] += yb;  s2k[2*p+1] += yb * yb;
                    if (w < N_POOL * P_POOL) {
                        int q = (w >= bnd) ? 1 : 0;
                        pa[q] += ya;
                        pb[q] += yb;
                    }
                }
            }
#pragma unroll
            for (int q = 0; q < 2; q++) {
                int pool = pool0 + q;
                if (pool < N_POOL) {
                    atomicAdd(&spool[ka * N_POOL + pool], pa[q] * 0.01f);
                    atomicAdd(&spool[kb * N_POOL + pool], pb[q] * 0.01f);
                }
            }
        }
    }

    // flush BN partials (each thread owns k0..k0+9; zero-adds from idle threads are harmless)
#pragma unroll
    for (int i = 0; i < KT; i++) {
        atomicAdd(&sb1[k0 + i], s1k[i]);
        atomicAdd(&sb2[k0 + i], s2k[i]);
    }
    __syncthreads();

    float* gp = g_pooled + (size_t)b * FEAT;
    for (int i = tid; i < FEAT; i += 256) gp[i] = spool[i];
    if (tid < K_OUT) {
        g_bnpart[(size_t)b * (2 * K_OUT) + tid]         = sb1[tid];
        g_bnpart[(size_t)b * (2 * K_OUT) + K_OUT + tid] = sb2[tid];
    }
}

// ---------------- pass 2: reduce BN stats -> scale/shift per channel ----------------
__global__ void bn_reduce_kernel(const float* __restrict__ gamma,
                                 const float* __restrict__ beta) {
    __shared__ float r1[256];
    __shared__ float r2[256];
    int k = blockIdx.x;
    int tid = threadIdx.x;
    float s1 = 0.0f, s2 = 0.0f;
    for (int b = tid; b < B_SIZE; b += 256) {
        s1 += g_bnpart[(size_t)b * (2 * K_OUT) + k];
        s2 += g_bnpart[(size_t)b * (2 * K_OUT) + K_OUT + k];
    }
    r1[tid] = s1;
    r2[tid] = s2;
    __syncthreads();
    for (int s = 128; s > 0; s >>= 1) {
        if (tid < s) { r1[tid] += r1[tid + s]; r2[tid] += r2[tid + s]; }
        __syncthreads();
    }
    if (tid == 0) {
        const float N = (float)((size_t)B_SIZE * W_OUT);
        float mean = r1[0] / N;
        float var  = r2[0] / N - mean * mean;
        float sc   = gamma[k] * rsqrtf(var + 1e-5f);
        g_scale[k] = sc;
        g_shift[k] = beta[k] - mean * sc;
    }
}

// ---------------- pass 3: subject-gathered FC ----------------
__global__ void fc_kernel(const float* __restrict__ x,
                          const float* __restrict__ fc_w,
                          const float* __restrict__ fc_b,
                          float* __restrict__ out) {
    int t = blockIdx.x * blockDim.x + threadIdx.x;
    if (t >= B_SIZE * O_OUT) return;
    int b = t >> 2;
    int o = t & 3;
    int sid = __float2int_rn(x[(size_t)b * (C_CH * T_FULL) + T_IN] * 1e-6f) - 1;
    const float* W  = fc_w + (size_t)sid * FEAT * O_OUT + o;
    const float* pf = g_pooled + (size_t)b * FEAT;
    float acc = fc_b[sid * O_OUT + o];
    for (int k = 0; k < K_OUT; k++) {
        float sc = g_scale[k];
        float sh = g_shift[k];
#pragma unroll
        for (int n = 0; n < N_POOL; n++) {
            int f = k * N_POOL + n;
            acc += (pf[f] * sc + sh) * W[(size_t)f * O_OUT];
        }
    }
    out[t] = acc;
}

// ---------------- launch ----------------
extern "C" void kernel_launch(void* const* d_in, const int* in_sizes, int n_in,
                              void* d_out, int out_size) {
    const float* x      = (const float*)d_in[0];
    const float* conv_w = (const float*)d_in[1];
    const float* conv_b = (const float*)d_in[2];
    const float* gamma  = (const float*)d_in[3];
    const float* beta   = (const float*)d_in[4];
    const float* fc_w   = (const float*)d_in[5];
    const float* fc_b   = (const float*)d_in[6];
    float* out = (float*)d_out;

    cudaFuncSetAttribute(conv_kernel,
                         cudaFuncAttributeMaxDynamicSharedMemorySize, SMEM_BYTES);

    transpose_w_kernel<<<(SW_ELEMS + 255) / 256, 256>>>(conv_w);
    conv_kernel<<<B_SIZE, 256, SMEM_BYTES>>>(x, conv_b);
    bn_reduce_kernel<<<K_OUT, 256>>>(gamma, beta);
    fc_kernel<<<(B_SIZE * O_OUT + 255) / 256, 256>>>(x, fc_w, fc_b, out);
}

// round 5
// speedup vs baseline: 2.0865x; 2.0865x over previous
#include <cuda_runtime.h>
#include <cstdint>

// ---------------- problem constants ----------------
#define B_SIZE 4096
#define C_CH   22
#define T_FULL 1002
#define T_IN   1001
#define K_OUT  40
#define KSZ    25
#define W_OUT  977
#define P_POOL 100
#define N_POOL 9
#define FEAT   360
#define O_OUT  4

// ---------------- tiling ----------------
#define CPAD   24                 // channels padded 22 -> 24 (3 k8 chunks)
#define XROW   1016               // x row stride in smem (mod 32 words = 24 -> conflict-free frags)
#define SX_F   (C_CH*XROW)        // 22352 floats
#define SW_F   (KSZ*CPAD*K_OUT)   // 24000 floats
#define NPAIR  31                 // m32 tiles covering w 0..991

// smem float offsets
#define SO_X     0
#define SO_W     SX_F                      // 22352
#define SO_POOL  (SO_W + SW_F)             // 46352
#define SO_B1    (SO_POOL + FEAT)          // 46712
#define SO_B2    (SO_B1 + K_OUT)           // 46752
#define SO_BIAS  (SO_B2 + K_OUT)           // 46792
#define SMEM_F   (SO_BIAS + K_OUT)         // 46832
#define SMEM_BYTES (SMEM_F*4)              // 187328

// ---------------- device scratch ----------------
__device__ float g_wt[SW_F];                           // [t][c24][k40], tf32-rounded
__device__ float g_pooled[(size_t)B_SIZE * FEAT];
__device__ float g_bnpart[(size_t)B_SIZE * 2 * K_OUT];
__device__ float g_scale[K_OUT];
__device__ float g_shift[K_OUT];

// ---------------- helpers ----------------
__device__ __forceinline__ uint32_t tf32r(float f) {
    uint32_t r;
    asm("cvt.rna.tf32.f32 %0, %1;" : "=r"(r) : "f"(f));
    return r;
}
__device__ __forceinline__ void mma_tf32(float* d,
                                         uint32_t a0, uint32_t a1, uint32_t a2, uint32_t a3,
                                         uint32_t b0, uint32_t b1) {
    asm volatile(
        "mma.sync.aligned.m16n8k8.row.col.f32.tf32.tf32.f32 "
        "{%0,%1,%2,%3}, {%4,%5,%6,%7}, {%8,%9}, {%0,%1,%2,%3};"
        : "+f"(d[0]), "+f"(d[1]), "+f"(d[2]), "+f"(d[3])
        : "r"(a0), "r"(a1), "r"(a2), "r"(a3), "r"(b0), "r"(b1));
}

// ---------------- pass 0: weights -> [t][c24][k40], tf32-rounded ----------------
__global__ void prep_w_kernel(const float* __restrict__ cw) {
    int idx = blockIdx.x * blockDim.x + threadIdx.x;
    if (idx >= SW_F) return;
    int t   = idx / (CPAD * K_OUT);
    int rem = idx - t * (CPAD * K_OUT);
    int c   = rem / K_OUT;
    int k   = rem - c * K_OUT;
    float v = 0.0f;
    if (c < C_CH) v = __uint_as_float(tf32r(cw[(k * C_CH + c) * KSZ + t]));
    g_wt[idx] = v;
}

// ---------------- pass 1: mma.sync conv + ELU + pool + BN partials ----------------
__global__ void __launch_bounds__(256, 1)
conv_mma_kernel(const float* __restrict__ x, const float* __restrict__ bias) {
    extern __shared__ float smem[];
    float* sx    = smem + SO_X;
    float* sw    = smem + SO_W;
    float* spool = smem + SO_POOL;
    float* sb1   = smem + SO_B1;
    float* sb2   = smem + SO_B2;
    float* sbias = smem + SO_BIAS;

    const int tid  = threadIdx.x;
    const int wid  = tid >> 5;
    const int lane = tid & 31;
    const int lg   = lane >> 2;       // group id (row)
    const int lt   = lane & 3;        // thread-in-group (col)
    const int b    = blockIdx.x;

    // stage x (tf32-rounded, zero-padded)
    const float* xg = x + (size_t)b * (C_CH * T_FULL);
    uint32_t* sxu = (uint32_t*)sx;
    for (int i = tid; i < SX_F; i += 256) {
        int c = i / XROW;
        int w = i - c * XROW;
        float v = (w < T_IN) ? xg[c * T_FULL + w] : 0.0f;
        sxu[i] = tf32r(v);
    }
    for (int i = tid; i < SW_F; i += 256) sw[i] = g_wt[i];
    for (int i = tid; i < FEAT + 2 * K_OUT; i += 256) spool[i] = 0.0f;
    if (tid < K_OUT) sbias[tid] = bias[tid];
    __syncthreads();

    for (int pair = wid; pair < NPAIR; pair += 8) {
        const int w0 = pair * 32;

        float acc[2][5][4];
#pragma unroll
        for (int ti = 0; ti < 2; ti++)
#pragma unroll
            for (int nt = 0; nt < 5; nt++)
#pragma unroll
                for (int r = 0; r < 4; r++) acc[ti][nt][r] = 0.0f;

        for (int t = 0; t < KSZ; t++) {
#pragma unroll
            for (int ck = 0; ck < 3; ck++) {
                // B fragments: W[t][ck*8 + krow][kcol]
                const uint32_t* wb = (const uint32_t*)(sw + (t * CPAD + ck * 8) * K_OUT);
                uint32_t bb[5][2];
#pragma unroll
                for (int nt = 0; nt < 5; nt++) {
                    int col = 8 * nt + lg;
                    bb[nt][0] = wb[lt * K_OUT + col];
                    bb[nt][1] = wb[(lt + 4) * K_OUT + col];
                }
                // A fragments: x[c][w0 + 16*tile + t + row]
                const uint32_t* xa = sxu + (ck * 8 + lt) * XROW + w0 + t + lg;
#pragma unroll
                for (int ti = 0; ti < 2; ti++) {
                    uint32_t a0 = xa[16 * ti];
                    uint32_t a1 = xa[16 * ti + 8];
                    uint32_t a2 = xa[16 * ti + 4 * XROW];
                    uint32_t a3 = xa[16 * ti + 4 * XROW + 8];
#pragma unroll
                    for (int nt = 0; nt < 5; nt++)
                        mma_tf32(acc[ti][nt], a0, a1, a2, a3, bb[nt][0], bb[nt][1]);
                }
            }
        }

        // epilogue: bias + ELU + BN stats + pooling, fragment-resident
        const int p0 = w0 / P_POOL;
#pragma unroll
        for (int nt = 0; nt < 5; nt++) {
#pragma unroll
            for (int rk = 0; rk < 2; rk++) {
                const int k = 8 * nt + 2 * lt + rk;
                const float bk = sbias[k];
                float s1 = 0.f, s2 = 0.f, q0 = 0.f, q1 = 0.f;
#pragma unroll
                for (int ti = 0; ti < 2; ti++) {
#pragma unroll
                    for (int rh = 0; rh < 2; rh++) {
                        int w = w0 + 16 * ti + lg + 8 * rh;
                        float v = acc[ti][nt][2 * rh + rk] + bk;
                        float y = v > 0.0f ? v : (__expf(v) - 1.0f);
                        if (w < W_OUT) {
                            s1 += y;
                            s2 += y * y;
                            if (w < N_POOL * P_POOL) {
                                float pv = y * 0.01f;
                                if (w / P_POOL == p0) q0 += pv; else q1 += pv;
                            }
                        }
                    }
                }
#pragma unroll
                for (int off = 4; off < 32; off <<= 1) {
                    s1 += __shfl_xor_sync(0xffffffffu, s1, off);
                    s2 += __shfl_xor_sync(0xffffffffu, s2, off);
                    q0 += __shfl_xor_sync(0xffffffffu, q0, off);
                    q1 += __shfl_xor_sync(0xffffffffu, q1, off);
                }
                if (lg == 0) {
                    atomicAdd(&sb1[k], s1);
                    atomicAdd(&sb2[k], s2);
                    if (p0 < N_POOL)     atomicAdd(&spool[k * N_POOL + p0], q0);
                    if (p0 + 1 < N_POOL) atomicAdd(&spool[k * N_POOL + p0 + 1], q1);
                }
            }
        }
    }
    __syncthreads();

    float* gp = g_pooled + (size_t)b * FEAT;
    for (int i = tid; i < FEAT; i += 256) gp[i] = spool[i];
    if (tid < K_OUT) {
        g_bnpart[(size_t)b * (2 * K_OUT) + tid]         = sb1[tid];
        g_bnpart[(size_t)b * (2 * K_OUT) + K_OUT + tid] = sb2[tid];
    }
}

// ---------------- pass 2: BN stats reduce ----------------
__global__ void bn_reduce_kernel(const float* __restrict__ gamma,
                                 const float* __restrict__ beta) {
    __shared__ float r1[256];
    __shared__ float r2[256];
    int k = blockIdx.x;
    int tid = threadIdx.x;
    float s1 = 0.0f, s2 = 0.0f;
    for (int b = tid; b < B_SIZE; b += 256) {
        s1 += g_bnpart[(size_t)b * (2 * K_OUT) + k];
        s2 += g_bnpart[(size_t)b * (2 * K_OUT) + K_OUT + k];
    }
    r1[tid] = s1; r2[tid] = s2;
    __syncthreads();
    for (int s = 128; s > 0; s >>= 1) {
        if (tid < s) { r1[tid] += r1[tid + s]; r2[tid] += r2[tid + s]; }
        __syncthreads();
    }
    if (tid == 0) {
        const float N = (float)((size_t)B_SIZE * W_OUT);
        float mean = r1[0] / N;
        float var  = r2[0] / N - mean * mean;
        float sc   = gamma[k] * rsqrtf(var + 1e-5f);
        g_scale[k] = sc;
        g_shift[k] = beta[k] - mean * sc;
    }
}

// ---------------- pass 3: subject-gathered FC (warp per sample) ----------------
__global__ void fc_kernel(const float* __restrict__ x,
                          const float* __restrict__ fc_w,
                          const float* __restrict__ fc_b,
                          float* __restrict__ out) {
    int wid  = threadIdx.x >> 5;
    int lane = threadIdx.x & 31;
    int b = blockIdx.x * 8 + wid;
    if (b >= B_SIZE) return;
    int sid = __float2int_rn(x[(size_t)b * (C_CH * T_FULL) + T_IN] * 1e-6f) - 1;
    const float4* Wp = (const float4*)(fc_w + (size_t)sid * FEAT * O_OUT);
    const float*  pf = g_pooled + (size_t)b * FEAT;
    float a0 = 0.f, a1 = 0.f, a2 = 0.f, a3 = 0.f;
#pragma unroll
    for (int j = 0; j < 12; j++) {
        int f = lane + j * 32;
        if (f < FEAT) {
            int k = f / N_POOL;
            float v = pf[f] * g_scale[k] + g_shift[k];
            float4 wv = Wp[f];
            a0 += v * wv.x; a1 += v * wv.y; a2 += v * wv.z; a3 += v * wv.w;
        }
    }
#pragma unroll
    for (int off = 16; off > 0; off >>= 1) {
        a0 += __shfl_xor_sync(0xffffffffu, a0, off);
        a1 += __shfl_xor_sync(0xffffffffu, a1, off);
        a2 += __shfl_xor_sync(0xffffffffu, a2, off);
        a3 += __shfl_xor_sync(0xffffffffu, a3, off);
    }
    if (lane == 0) {
        const float* fb = fc_b + sid * O_OUT;
        float4 o = make_float4(a0 + fb[0], a1 + fb[1], a2 + fb[2], a3 + fb[3]);
        ((float4*)out)[b] = o;
    }
}

// ---------------- launch ----------------
extern "C" void kernel_launch(void* const* d_in, const int* in_sizes, int n_in,
                              void* d_out, int out_size) {
    const float* x      = (const float*)d_in[0];
    const float* conv_w = (const float*)d_in[1];
    const float* conv_b = (const float*)d_in[2];
    const float* gamma  = (const float*)d_in[3];
    const float* beta   = (const float*)d_in[4];
    const float* fc_w   = (const float*)d_in[5];
    const float* fc_b   = (const float*)d_in[6];
    float* out = (float*)d_out;

    cudaFuncSetAttribute(conv_mma_kernel,
                         cudaFuncAttributeMaxDynamicSharedMemorySize, SMEM_BYTES);

    prep_w_kernel<<<(SW_F + 255) / 256, 256>>>(conv_w);
    conv_mma_kernel<<<B_SIZE, 256, SMEM_BYTES>>>(x, conv_b);
    bn_reduce_kernel<<<K_OUT, 256>>>(gamma, beta);
    fc_kernel<<<B_SIZE / 8, 256>>>(x, fc_w, fc_b, out);
}

// round 9
// speedup vs baseline: 3.0782x; 1.4753x over previous
#include <cuda_runtime.h>
#include <cstdint>

// ---------------- problem constants ----------------
#define B_SIZE 4096
#define C_CH   22
#define T_FULL 1002
#define T_IN   1001
#define K_OUT  40
#define KSZ    25
#define W_OUT  977
#define P_POOL 100
#define N_POOL 9
#define FEAT   360
#define O_OUT  4

// ---------------- tiling ----------------
#define CPAD   24                 // channels padded 22 -> 24 (3 k8 chunks)
#define XROW   1016               // x row stride in smem (mod 32 words = 24 -> conflict-free frags)
#define SX_F   (C_CH*XROW)        // 22352 floats
#define SW_F   (KSZ*CPAD*K_OUT)   // 24000 floats
#define NPAIR  31                 // m32 tiles covering w 0..991
#define NTHR   512
#define NWARP  16

// smem float offsets
#define SO_X     0
#define SO_W     SX_F                      // 22352
#define SO_POOL  (SO_W + SW_F)             // 46352
#define SO_B1    (SO_POOL + FEAT)          // 46712
#define SO_B2    (SO_B1 + K_OUT)           // 46752
#define SO_BIAS  (SO_B2 + K_OUT)           // 46792
#define SMEM_F   (SO_BIAS + K_OUT)         // 46832
#define SMEM_BYTES (SMEM_F*4)              // 187328

// ---------------- device scratch ----------------
__device__ float g_wt[SW_F];                           // [t][c24][k40], tf32-rounded
__device__ float g_pooled[(size_t)B_SIZE * FEAT];
__device__ float g_bnpart[(size_t)B_SIZE * 2 * K_OUT];
__device__ float g_scale[K_OUT];
__device__ float g_shift[K_OUT];

// ---------------- helpers ----------------
__device__ __forceinline__ uint32_t tf32r(float f) {
    uint32_t r;
    asm("cvt.rna.tf32.f32 %0, %1;" : "=r"(r) : "f"(f));
    return r;
}
__device__ __forceinline__ void mma_tf32(float* d,
                                         uint32_t a0, uint32_t a1, uint32_t a2, uint32_t a3,
                                         uint32_t b0, uint32_t b1) {
    asm volatile(
        "mma.sync.aligned.m16n8k8.row.col.f32.tf32.tf32.f32 "
        "{%0,%1,%2,%3}, {%4,%5,%6,%7}, {%8,%9}, {%0,%1,%2,%3};"
        : "+f"(d[0]), "+f"(d[1]), "+f"(d[2]), "+f"(d[3])
        : "r"(a0), "r"(a1), "r"(a2), "r"(a3), "r"(b0), "r"(b1));
}

// ---------------- pass 0: weights -> [t][c24][k40], tf32-rounded ----------------
__global__ void prep_w_kernel(const float* __restrict__ cw) {
    int idx = blockIdx.x * blockDim.x + threadIdx.x;
    if (idx >= SW_F) return;
    int t   = idx / (CPAD * K_OUT);
    int rem = idx - t * (CPAD * K_OUT);
    int c   = rem / K_OUT;
    int k   = rem - c * K_OUT;
    float v = 0.0f;
    if (c < C_CH) v = __uint_as_float(tf32r(cw[(k * C_CH + c) * KSZ + t]));
    g_wt[idx] = v;
}

// ---------------- pass 1: mma.sync conv + ELU + pool + BN partials ----------------
__global__ void __launch_bounds__(NTHR, 1)
conv_mma_kernel(const float* __restrict__ x, const float* __restrict__ bias) {
    extern __shared__ float smem[];
    float* sx    = smem + SO_X;
    float* sw    = smem + SO_W;
    float* spool = smem + SO_POOL;
    float* sb1   = smem + SO_B1;
    float* sb2   = smem + SO_B2;
    float* sbias = smem + SO_BIAS;

    const int tid  = threadIdx.x;
    const int wid  = tid >> 5;        // 0..15
    const int lane = tid & 31;
    const int lg   = lane >> 2;       // group id (row)
    const int lt   = lane & 3;        // thread-in-group (col)
    const int b    = blockIdx.x;

    // stage x (tf32-rounded, zero-padded)
    const float* xg = x + (size_t)b * (C_CH * T_FULL);
    uint32_t* sxu = (uint32_t*)sx;
    for (int i = tid; i < SX_F; i += NTHR) {
        int c = i / XROW;
        int w = i - c * XROW;
        float v = (w < T_IN) ? xg[c * T_FULL + w] : 0.0f;
        sxu[i] = tf32r(v);
    }
    for (int i = tid; i < SW_F; i += NTHR) sw[i] = g_wt[i];
    for (int i = tid; i < FEAT + 2 * K_OUT; i += NTHR) spool[i] = 0.0f;
    if (tid < K_OUT) sbias[tid] = bias[tid];
    __syncthreads();

    // each warp owns pair tiles {wid, wid+16}; second may be absent (NPAIR=31)
    const int w0a  = wid * 32;
    const int w0b  = (wid + NWARP) * 32;
    const bool has1 = (wid + NWARP) < NPAIR;

    float acc[2][2][5][4];
#pragma unroll
    for (int pr = 0; pr < 2; pr++)
#pragma unroll
        for (int ti = 0; ti < 2; ti++)
#pragma unroll
            for (int nt = 0; nt < 5; nt++)
#pragma unroll
                for (int r = 0; r < 4; r++) acc[pr][ti][nt][r] = 0.0f;

    for (int t = 0; t < KSZ; t++) {
#pragma unroll
        for (int ck = 0; ck < 3; ck++) {
            // B fragments once per (t, ck) — shared by both pair tiles
            const uint32_t* wb = (const uint32_t*)(sw + (t * CPAD + ck * 8) * K_OUT);
            uint32_t bb[5][2];
#pragma unroll
            for (int nt = 0; nt < 5; nt++) {
                int col = 8 * nt + lg;
                bb[nt][0] = wb[lt * K_OUT + col];
                bb[nt][1] = wb[(lt + 4) * K_OUT + col];
            }
            const uint32_t* xbase = sxu + (ck * 8 + lt) * XROW + t + lg;
            // pair 0
            {
                const uint32_t* xa = xbase + w0a;
#pragma unroll
                for (int ti = 0; ti < 2; ti++) {
                    uint32_t a0 = xa[16 * ti];
                    uint32_t a1 = xa[16 * ti + 8];
                    uint32_t a2 = xa[16 * ti + 4 * XROW];
                    uint32_t a3 = xa[16 * ti + 4 * XROW + 8];
#pragma unroll
                    for (int nt = 0; nt < 5; nt++)
                        mma_tf32(acc[0][ti][nt], a0, a1, a2, a3, bb[nt][0], bb[nt][1]);
                }
            }
            // pair 1
            if (has1) {
                const uint32_t* xa = xbase + w0b;
#pragma unroll
                for (int ti = 0; ti < 2; ti++) {
                    uint32_t a0 = xa[16 * ti];
                    uint32_t a1 = xa[16 * ti + 8];
                    uint32_t a2 = xa[16 * ti + 4 * XROW];
                    uint32_t a3 = xa[16 * ti + 4 * XROW + 8];
#pragma unroll
                    for (int nt = 0; nt < 5; nt++)
                        mma_tf32(acc[1][ti][nt], a0, a1, a2, a3, bb[nt][0], bb[nt][1]);
                }
            }
        }
    }

    // epilogue: bias + ELU + BN stats + pooling, fragment-resident
#pragma unroll
    for (int pr = 0; pr < 2; pr++) {
        if (pr == 1 && !has1) break;
        const int w0 = pr ? w0b : w0a;
        const int p0 = w0 / P_POOL;
#pragma unroll
        for (int nt = 0; nt < 5; nt++) {
#pragma unroll
            for (int rk = 0; rk < 2; rk++) {
                const int k = 8 * nt + 2 * lt + rk;
                const float bk = sbias[k];
                float s1 = 0.f, s2 = 0.f, q0 = 0.f, q1 = 0.f;
#pragma unroll
                for (int ti = 0; ti < 2; ti++) {
#pragma unroll
                    for (int rh = 0; rh < 2; rh++) {
                        int w = w0 + 16 * ti + lg + 8 * rh;
                        float v = acc[pr][ti][nt][2 * rh + rk] + bk;
                        float y = v > 0.0f ? v : (__expf(v) - 1.0f);
                        if (w < W_OUT) {
                            s1 += y;
                            s2 += y * y;
                            if (w < N_POOL * P_POOL) {
                                float pv = y * 0.01f;
                                if (w / P_POOL == p0) q0 += pv; else q1 += pv;
                            }
                        }
                    }
                }
#pragma unroll
                for (int off = 4; off < 32; off <<= 1) {
                    s1 += __shfl_xor_sync(0xffffffffu, s1, off);
                    s2 += __shfl_xor_sync(0xffffffffu, s2, off);
                    q0 += __shfl_xor_sync(0xffffffffu, q0, off);
                    q1 += __shfl_xor_sync(0xffffffffu, q1, off);
                }
                if (lg == 0) {
                    atomicAdd(&sb1[k], s1);
                    atomicAdd(&sb2[k], s2);
                    if (p0 < N_POOL)     atomicAdd(&spool[k * N_POOL + p0], q0);
                    if (p0 + 1 < N_POOL) atomicAdd(&spool[k * N_POOL + p0 + 1], q1);
                }
            }
        }
    }
    __syncthreads();

    float* gp = g_pooled + (size_t)b * FEAT;
    for (int i = tid; i < FEAT; i += NTHR) gp[i] = spool[i];
    if (tid < K_OUT) {
        g_bnpart[(size_t)b * (2 * K_OUT) + tid]         = sb1[tid];
        g_bnpart[(size_t)b * (2 * K_OUT) + K_OUT + tid] = sb2[tid];
    }
}

// ---------------- pass 2: BN stats reduce ----------------
__global__ void bn_reduce_kernel(const float* __restrict__ gamma,
                                 const float* __restrict__ beta) {
    __shared__ float r1[256];
    __shared__ float r2[256];
    int k = blockIdx.x;
    int tid = threadIdx.x;
    float s1 = 0.0f, s2 = 0.0f;
    for (int b = tid; b < B_SIZE; b += 256) {
        s1 += g_bnpart[(size_t)b * (2 * K_OUT) + k];
        s2 += g_bnpart[(size_t)b * (2 * K_OUT) + K_OUT + k];
    }
    r1[tid] = s1; r2[tid] = s2;
    __syncthreads();
    for (int s = 128; s > 0; s >>= 1) {
        if (tid < s) { r1[tid] += r1[tid + s]; r2[tid] += r2[tid + s]; }
        __syncthreads();
    }
    if (tid == 0) {
        const float N = (float)((size_t)B_SIZE * W_OUT);
        float mean = r1[0] / N;
        float var  = r2[0] / N - mean * mean;
        float sc   = gamma[k] * rsqrtf(var + 1e-5f);
        g_scale[k] = sc;
        g_shift[k] = beta[k] - mean * sc;
    }
}

// ---------------- pass 3: subject-gathered FC (warp per sample) ----------------
__global__ void fc_kernel(const float* __restrict__ x,
                          const float* __restrict__ fc_w,
                          const float* __restrict__ fc_b,
                          float* __restrict__ out) {
    int wid  = threadIdx.x >> 5;
    int lane = threadIdx.x & 31;
    int b = blockIdx.x * 8 + wid;
    if (b >= B_SIZE) return;
    int sid = __float2int_rn(x[(size_t)b * (C_CH * T_FULL) + T_IN] * 1e-6f) - 1;
    const float4* Wp = (const float4*)(fc_w + (size_t)sid * FEAT * O_OUT);
    const float*  pf = g_pooled + (size_t)b * FEAT;
    float a0 = 0.f, a1 = 0.f, a2 = 0.f, a3 = 0.f;
#pragma unroll
    for (int j = 0; j < 12; j++) {
        int f = lane + j * 32;
        if (f < FEAT) {
            int k = f / N_POOL;
            float v = pf[f] * g_scale[k] + g_shift[k];
            float4 wv = Wp[f];
            a0 += v * wv.x; a1 += v * wv.y; a2 += v * wv.z; a3 += v * wv.w;
        }
    }
#pragma unroll
    for (int off = 16; off > 0; off >>= 1) {
        a0 += __shfl_xor_sync(0xffffffffu, a0, off);
        a1 += __shfl_xor_sync(0xffffffffu, a1, off);
        a2 += __shfl_xor_sync(0xffffffffu, a2, off);
        a3 += __shfl_xor_sync(0xffffffffu, a3, off);
    }
    if (lane == 0) {
        const float* fb = fc_b + sid * O_OUT;
        float4 o = make_float4(a0 + fb[0], a1 + fb[1], a2 + fb[2], a3 + fb[3]);
        ((float4*)out)[b] = o;
    }
}

// ---------------- launch ----------------
extern "C" void kernel_launch(void* const* d_in, const int* in_sizes, int n_in,
                              void* d_out, int out_size) {
    const float* x      = (const float*)d_in[0];
    const float* conv_w = (const float*)d_in[1];
    const float* conv_b = (const float*)d_in[2];
    const float* gamma  = (const float*)d_in[3];
    const float* beta   = (const float*)d_in[4];
    const float* fc_w   = (const float*)d_in[5];
    const float* fc_b   = (const float*)d_in[6];
    float* out = (float*)d_out;

    cudaFuncSetAttribute(conv_mma_kernel,
                         cudaFuncAttributeMaxDynamicSharedMemorySize, SMEM_BYTES);

    prep_w_kernel<<<(SW_F + 255) / 256, 256>>>(conv_w);
    conv_mma_kernel<<<B_SIZE, NTHR, SMEM_BYTES>>>(x, conv_b);
    bn_reduce_kernel<<<K_OUT, 256>>>(gamma, beta);
    fc_kernel<<<B_SIZE / 8, 256>>>(x, fc_w, fc_b, out);
}

// round 10
// speedup vs baseline: 4.1678x; 1.3540x over previous
#include <cuda_runtime.h>
#include <cuda_fp16.h>
#include <cstdint>

// ---------------- problem constants ----------------
#define B_SIZE 4096
#define C_CH   22
#define T_FULL 1002
#define T_IN   1001
#define K_OUT  40
#define KSZ    25
#define W_OUT  977
#define P_POOL 100
#define N_POOL 9
#define FEAT   360
#define O_OUT  4

// ---------------- tiling ----------------
#define CP2    16                 // channel pairs (32 channels, 22 real)
#define XROWH  1016               // x row stride in half2 units (mod 32 = 24 -> conflict-free)
#define SXH2   (CP2*XROWH)        // 16256 half2
#define SWH2   (KSZ*CP2*K_OUT)    // 16000 half2
#define NPAIR  31                 // m32 tiles covering w 0..991
#define NTHR   512
#define NWARP  16

// smem byte offsets
#define SM_X     0
#define SM_W     (SXH2*4)                  // 65024
#define SM_POOL  (SM_W + SWH2*4)           // 129024
#define SM_B1    (SM_POOL + FEAT*4)        // 130464
#define SM_B2    (SM_B1 + K_OUT*4)         // 130624
#define SM_BIAS  (SM_B2 + K_OUT*4)         // 130784
#define SMEM_BYTES (SM_BIAS + K_OUT*4)     // 130944

// ---------------- device scratch ----------------
__device__ uint32_t g_wh2[SWH2];                       // [t][cp16][k40] half2
__device__ float g_pooled[(size_t)B_SIZE * FEAT];
__device__ float g_bnpart[(size_t)B_SIZE * 2 * K_OUT];
__device__ float g_scale[K_OUT];
__device__ float g_shift[K_OUT];

// ---------------- helpers ----------------
__device__ __forceinline__ void mma_f16(float* d,
                                        uint32_t a0, uint32_t a1, uint32_t a2, uint32_t a3,
                                        uint32_t b0, uint32_t b1) {
    asm volatile(
        "mma.sync.aligned.m16n8k16.row.col.f32.f16.f16.f32 "
        "{%0,%1,%2,%3}, {%4,%5,%6,%7}, {%8,%9}, {%0,%1,%2,%3};"
        : "+f"(d[0]), "+f"(d[1]), "+f"(d[2]), "+f"(d[3])
        : "r"(a0), "r"(a1), "r"(a2), "r"(a3), "r"(b0), "r"(b1));
}

// ---------------- pass 0: weights -> [t][cp16][k40] half2 ----------------
__global__ void prep_w_kernel(const float* __restrict__ cw) {
    int idx = blockIdx.x * blockDim.x + threadIdx.x;
    if (idx >= SWH2) return;
    int t   = idx / (CP2 * K_OUT);
    int rem = idx - t * (CP2 * K_OUT);
    int cp  = rem / K_OUT;
    int k   = rem - cp * K_OUT;
    int c0 = 2 * cp, c1 = 2 * cp + 1;
    float v0 = (c0 < C_CH) ? cw[(k * C_CH + c0) * KSZ + t] : 0.0f;
    float v1 = (c1 < C_CH) ? cw[(k * C_CH + c1) * KSZ + t] : 0.0f;
    half2 h = __floats2half2_rn(v0, v1);
    g_wh2[idx] = *(uint32_t*)&h;
}

// ---------------- pass 1: f16 mma conv + ELU + pool + BN partials ----------------
__global__ void __launch_bounds__(NTHR, 1)
conv_mma_kernel(const float* __restrict__ x, const float* __restrict__ bias) {
    extern __shared__ char smemc[];
    uint32_t* sxh2  = (uint32_t*)(smemc + SM_X);
    uint32_t* swh2  = (uint32_t*)(smemc + SM_W);
    float*    spool = (float*)(smemc + SM_POOL);
    float*    sb1   = (float*)(smemc + SM_B1);
    float*    sb2   = (float*)(smemc + SM_B2);
    float*    sbias = (float*)(smemc + SM_BIAS);

    const int tid  = threadIdx.x;
    const int wid  = tid >> 5;        // 0..15
    const int lane = tid & 31;
    const int lg   = lane >> 2;       // group id (w row)
    const int lt   = lane & 3;        // thread-in-group
    const int b    = blockIdx.x;

    // stage x as half2 channel pairs (zero-padded)
    const float* xg = x + (size_t)b * (C_CH * T_FULL);
    for (int i = tid; i < SXH2; i += NTHR) {
        int cp = i / XROWH;
        int w  = i - cp * XROWH;
        int c0 = 2 * cp, c1 = c0 + 1;
        float v0 = (c0 < C_CH && w < T_IN) ? xg[c0 * T_FULL + w] : 0.0f;
        float v1 = (c1 < C_CH && w < T_IN) ? xg[c1 * T_FULL + w] : 0.0f;
        half2 h = __floats2half2_rn(v0, v1);
        sxh2[i] = *(uint32_t*)&h;
    }
    for (int i = tid; i < SWH2; i += NTHR) swh2[i] = g_wh2[i];
    for (int i = tid; i < FEAT + 2 * K_OUT; i += NTHR) spool[i] = 0.0f;
    if (tid < K_OUT) sbias[tid] = bias[tid];
    __syncthreads();

    // each warp owns pair tiles {wid, wid+16}; second may be absent (NPAIR=31)
    const int w0a  = wid * 32;
    const int w0b  = (wid + NWARP) * 32;
    const bool has1 = (wid + NWARP) < NPAIR;

    float acc[2][2][5][4];
#pragma unroll
    for (int pr = 0; pr < 2; pr++)
#pragma unroll
        for (int ti = 0; ti < 2; ti++)
#pragma unroll
            for (int nt = 0; nt < 5; nt++)
#pragma unroll
                for (int r = 0; r < 4; r++) acc[pr][ti][nt][r] = 0.0f;

    for (int t = 0; t < KSZ; t++) {
#pragma unroll
        for (int ck = 0; ck < 2; ck++) {
            // B fragments once per (t, ck) — shared by both pair tiles
            const uint32_t* wb = swh2 + (t * CP2 + ck * 8) * K_OUT;
            uint32_t bb[5][2];
#pragma unroll
            for (int nt = 0; nt < 5; nt++) {
                int col = 8 * nt + lg;
                bb[nt][0] = wb[lt * K_OUT + col];
                bb[nt][1] = wb[(lt + 4) * K_OUT + col];
            }
            const uint32_t* xlo = sxh2 + (ck * 8 + lt) * XROWH + t + lg;
            const uint32_t* xhi = xlo + 4 * XROWH;      // cp + 4 (k 8..15)
            // pair 0
            {
#pragma unroll
                for (int ti = 0; ti < 2; ti++) {
                    int o = w0a + 16 * ti;
                    uint32_t a0 = xlo[o];
                    uint32_t a1 = xlo[o + 8];
                    uint32_t a2 = xhi[o];
                    uint32_t a3 = xhi[o + 8];
#pragma unroll
                    for (int nt = 0; nt < 5; nt++)
                        mma_f16(acc[0][ti][nt], a0, a1, a2, a3, bb[nt][0], bb[nt][1]);
                }
            }
            // pair 1
            if (has1) {
#pragma unroll
                for (int ti = 0; ti < 2; ti++) {
                    int o = w0b + 16 * ti;
                    uint32_t a0 = xlo[o];
                    uint32_t a1 = xlo[o + 8];
                    uint32_t a2 = xhi[o];
                    uint32_t a3 = xhi[o + 8];
#pragma unroll
                    for (int nt = 0; nt < 5; nt++)
                        mma_f16(acc[1][ti][nt], a0, a1, a2, a3, bb[nt][0], bb[nt][1]);
                }
            }
        }
    }

    // epilogue: bias + ELU + BN stats + pooling, fragment-resident
#pragma unroll
    for (int pr = 0; pr < 2; pr++) {
        if (pr == 1 && !has1) break;
        const int w0 = pr ? w0b : w0a;
        const int p0 = w0 / P_POOL;
#pragma unroll
        for (int nt = 0; nt < 5; nt++) {
#pragma unroll
            for (int rk = 0; rk < 2; rk++) {
                const int k = 8 * nt + 2 * lt + rk;
                const float bk = sbias[k];
                float s1 = 0.f, s2 = 0.f, q0 = 0.f, q1 = 0.f;
#pragma unroll
                for (int ti = 0; ti < 2; ti++) {
#pragma unroll
                    for (int rh = 0; rh < 2; rh++) {
                        int w = w0 + 16 * ti + lg + 8 * rh;
                        float v = acc[pr][ti][nt][2 * rh + rk] + bk;
                        float y = v > 0.0f ? v : (__expf(v) - 1.0f);
                        if (w < W_OUT) {
                            s1 += y;
                            s2 += y * y;
                            if (w < N_POOL * P_POOL) {
                                float pv = y * 0.01f;
                                if (w / P_POOL == p0) q0 += pv; else q1 += pv;
                            }
                        }
                    }
                }
#pragma unroll
                for (int off = 4; off < 32; off <<= 1) {
                    s1 += __shfl_xor_sync(0xffffffffu, s1, off);
                    s2 += __shfl_xor_sync(0xffffffffu, s2, off);
                    q0 += __shfl_xor_sync(0xffffffffu, q0, off);
                    q1 += __shfl_xor_sync(0xffffffffu, q1, off);
                }
                if (lg == 0) {
                    atomicAdd(&sb1[k], s1);
                    atomicAdd(&sb2[k], s2);
                    if (p0 < N_POOL)     atomicAdd(&spool[k * N_POOL + p0], q0);
                    if (p0 + 1 < N_POOL) atomicAdd(&spool[k * N_POOL + p0 + 1], q1);
                }
            }
        }
    }
    __syncthreads();

    float* gp = g_pooled + (size_t)b * FEAT;
    for (int i = tid; i < FEAT; i += NTHR) gp[i] = spool[i];
    if (tid < K_OUT) {
        g_bnpart[(size_t)b * (2 * K_OUT) + tid]         = sb1[tid];
        g_bnpart[(size_t)b * (2 * K_OUT) + K_OUT + tid] = sb2[tid];
    }
}

// ---------------- pass 2: BN stats reduce ----------------
__global__ void bn_reduce_kernel(const float* __restrict__ gamma,
                                 const float* __restrict__ beta) {
    __shared__ float r1[256];
    __shared__ float r2[256];
    int k = blockIdx.x;
    int tid = threadIdx.x;
    float s1 = 0.0f, s2 = 0.0f;
    for (int b = tid; b < B_SIZE; b += 256) {
        s1 += g_bnpart[(size_t)b * (2 * K_OUT) + k];
        s2 += g_bnpart[(size_t)b * (2 * K_OUT) + K_OUT + k];
    }
    r1[tid] = s1; r2[tid] = s2;
    __syncthreads();
    for (int s = 128; s > 0; s >>= 1) {
        if (tid < s) { r1[tid] += r1[tid + s]; r2[tid] += r2[tid + s]; }
        __syncthreads();
    }
    if (tid == 0) {
        const float N = (float)((size_t)B_SIZE * W_OUT);
        float mean = r1[0] / N;
        float var  = r2[0] / N - mean * mean;
        float sc   = gamma[k] * rsqrtf(var + 1e-5f);
        g_scale[k] = sc;
        g_shift[k] = beta[k] - mean * sc;
    }
}

// ---------------- pass 3: subject-gathered FC (warp per sample) ----------------
__global__ void fc_kernel(const float* __restrict__ x,
                          const float* __restrict__ fc_w,
                          const float* __restrict__ fc_b,
                          float* __restrict__ out) {
    int wid  = threadIdx.x >> 5;
    int lane = threadIdx.x & 31;
    int b = blockIdx.x * 8 + wid;
    if (b >= B_SIZE) return;
    int sid = __float2int_rn(x[(size_t)b * (C_CH * T_FULL) + T_IN] * 1e-6f) - 1;
    const float4* Wp = (const float4*)(fc_w + (size_t)sid * FEAT * O_OUT);
    const float*  pf = g_pooled + (size_t)b * FEAT;
    float a0 = 0.f, a1 = 0.f, a2 = 0.f, a3 = 0.f;
#pragma unroll
    for (int j = 0; j < 12; j++) {
        int f = lane + j * 32;
        if (f < FEAT) {
            int k = f / N_POOL;
            float v = pf[f] * g_scale[k] + g_shift[k];
            float4 wv = Wp[f];
            a0 += v * wv.x; a1 += v * wv.y; a2 += v * wv.z; a3 += v * wv.w;
        }
    }
#pragma unroll
    for (int off = 16; off > 0; off >>= 1) {
        a0 += __shfl_xor_sync(0xffffffffu, a0, off);
        a1 += __shfl_xor_sync(0xffffffffu, a1, off);
        a2 += __shfl_xor_sync(0xffffffffu, a2, off);
        a3 += __shfl_xor_sync(0xffffffffu, a3, off);
    }
    if (lane == 0) {
        const float* fb = fc_b + sid * O_OUT;
        float4 o = make_float4(a0 + fb[0], a1 + fb[1], a2 + fb[2], a3 + fb[3]);
        ((float4*)out)[b] = o;
    }
}

// ---------------- launch ----------------
extern "C" void kernel_launch(void* const* d_in, const int* in_sizes, int n_in,
                              void* d_out, int out_size) {
    const float* x      = (const float*)d_in[0];
    const float* conv_w = (const float*)d_in[1];
    const float* conv_b = (const float*)d_in[2];
    const float* gamma  = (const float*)d_in[3];
    const float* beta   = (const float*)d_in[4];
    const float* fc_w   = (const float*)d_in[5];
    const float* fc_b   = (const float*)d_in[6];
    float* out = (float*)d_out;

    cudaFuncSetAttribute(conv_mma_kernel,
                         cudaFuncAttributeMaxDynamicSharedMemorySize, SMEM_BYTES);

    prep_w_kernel<<<(SWH2 + 255) / 256, 256>>>(conv_w);
    conv_mma_kernel<<<B_SIZE, NTHR, SMEM_BYTES>>>(x, conv_b);
    bn_reduce_kernel<<<K_OUT, 256>>>(gamma, beta);
    fc_kernel<<<B_SIZE / 8, 256>>>(x, fc_w, fc_b, out);
}

// round 11
// speedup vs baseline: 4.3509x; 1.0439x over previous
#include <cuda_runtime.h>
#include <cuda_fp16.h>
#include <cstdint>

// ---------------- problem constants ----------------
#define B_SIZE 4096
#define C_CH   22
#define T_FULL 1002
#define T_IN   1001
#define K_OUT  40
#define KSZ    25
#define W_OUT  977
#define P_POOL 100
#define N_POOL 9
#define FEAT   360
#define O_OUT  4

// ---------------- tiling ----------------
#define TP     13                 // tap pairs (25 taps, last padded)
#define CPAD   24                 // channels padded 22 -> 24 (3 chunks of 8)
#define XP     516                // half2 per phase array (516 mod 32 = 4)
#define XROW2  (2*XP)             // half2 per channel row (1032, mod 32 = 8)
#define SXH2   (CPAD*XROW2)       // 24768 half2
#define SWH2   (TP*CPAD*K_OUT)    // 12480 half2
#define NPAIR  31                 // m32 tiles covering w 0..991
#define NTHR   512
#define NWARP  16

// smem byte offsets
#define SM_X     0
#define SM_W     (SXH2*4)                  // 99072
#define SM_POOL  (SM_W + SWH2*4)           // 148992
#define SM_B1    (SM_POOL + FEAT*4)        // 150432
#define SM_B2    (SM_B1 + K_OUT*4)         // 150592
#define SM_BIAS  (SM_B2 + K_OUT*4)         // 150752
#define SMEM_BYTES (SM_BIAS + K_OUT*4)     // 150912

// ---------------- device scratch ----------------
__device__ uint32_t g_wh2[SWH2];                       // [tp][c24][k40] half2 = (w[t0], w[t0+1])
__device__ float g_pooled[(size_t)B_SIZE * FEAT];
__device__ float g_bnpart[(size_t)B_SIZE * 2 * K_OUT];
__device__ float g_scale[K_OUT];
__device__ float g_shift[K_OUT];

// ---------------- helpers ----------------
__device__ __forceinline__ void mma_f16(float* d,
                                        uint32_t a0, uint32_t a1, uint32_t a2, uint32_t a3,
                                        uint32_t b0, uint32_t b1) {
    asm volatile(
        "mma.sync.aligned.m16n8k16.row.col.f32.f16.f16.f32 "
        "{%0,%1,%2,%3}, {%4,%5,%6,%7}, {%8,%9}, {%0,%1,%2,%3};"
        : "+f"(d[0]), "+f"(d[1]), "+f"(d[2]), "+f"(d[3])
        : "r"(a0), "r"(a1), "r"(a2), "r"(a3), "r"(b0), "r"(b1));
}

// ---------------- pass 0: weights -> [tp][c24][k40] tap-pair half2 ----------------
__global__ void prep_w_kernel(const float* __restrict__ cw) {
    int idx = blockIdx.x * blockDim.x + threadIdx.x;
    if (idx >= SWH2) return;
    int tp  = idx / (CPAD * K_OUT);
    int rem = idx - tp * (CPAD * K_OUT);
    int c   = rem / K_OUT;
    int k   = rem - c * K_OUT;
    int t0 = 2 * tp, t1 = 2 * tp + 1;
    float v0 = (c < C_CH) ? cw[(k * C_CH + c) * KSZ + t0] : 0.0f;
    float v1 = (c < C_CH && t1 < KSZ) ? cw[(k * C_CH + c) * KSZ + t1] : 0.0f;
    half2 h = __floats2half2_rn(v0, v1);
    g_wh2[idx] = *(uint32_t*)&h;
}

// ---------------- pass 1: f16 mma conv + ELU + pool + BN partials ----------------
__global__ void __launch_bounds__(NTHR, 1)
conv_mma_kernel(const float* __restrict__ x, const float* __restrict__ bias) {
    extern __shared__ char smemc[];
    uint32_t* sxh2  = (uint32_t*)(smemc + SM_X);
    uint32_t* swh2  = (uint32_t*)(smemc + SM_W);
    float*    spool = (float*)(smemc + SM_POOL);
    float*    sb1   = (float*)(smemc + SM_B1);
    float*    sb2   = (float*)(smemc + SM_B2);
    float*    sbias = (float*)(smemc + SM_BIAS);

    const int tid  = threadIdx.x;
    const int wid  = tid >> 5;        // 0..15
    const int lane = tid & 31;
    const int lg   = lane >> 2;       // group id (w row)
    const int lt   = lane & 3;        // thread-in-group
    const int b    = blockIdx.x;

    // stage x as two phase-shifted half2 arrays per channel:
    //   phase0[c][i] = (x[c,2i],   x[c,2i+1])
    //   phase1[c][i] = (x[c,2i+1], x[c,2i+2])
    const float* xg = x + (size_t)b * (C_CH * T_FULL);
    for (int i = tid; i < SXH2; i += NTHR) {
        int c   = i / XROW2;
        int rem = i - c * XROW2;
        int ph  = rem >= XP;
        int j   = rem - ph * XP;
        int w0h = 2 * j + ph;
        float v0 = (c < C_CH && w0h < T_IN) ? xg[c * T_FULL + w0h] : 0.0f;
        float v1 = (c < C_CH && w0h + 1 < T_IN) ? xg[c * T_FULL + w0h + 1] : 0.0f;
        half2 h = __floats2half2_rn(v0, v1);
        sxh2[i] = *(uint32_t*)&h;
    }
    for (int i = tid; i < SWH2; i += NTHR) swh2[i] = g_wh2[i];
    for (int i = tid; i < FEAT + 2 * K_OUT; i += NTHR) spool[i] = 0.0f;
    if (tid < K_OUT) sbias[tid] = bias[tid];
    __syncthreads();

    // each warp owns pair tiles {wid, wid+16}; second may be absent (NPAIR=31)
    const int w0a  = wid * 32;
    const int w0b  = (wid + NWARP) * 32;
    const bool has1 = (wid + NWARP) < NPAIR;

    // loop-invariant per-thread A offsets: off = (wbase>>1) + (wbase&1)*XP,
    // wbase = w0 + 16*ti + lg  (parity = lg&1, constant)
    const int phoff = (lg & 1) * XP;
    int offA[2][2];
#pragma unroll
    for (int pr = 0; pr < 2; pr++)
#pragma unroll
        for (int ti = 0; ti < 2; ti++) {
            int wbase = (pr ? w0b : w0a) + 16 * ti + lg;
            offA[pr][ti] = (wbase >> 1) + phoff;
        }

    float acc[2][2][5][4];
#pragma unroll
    for (int pr = 0; pr < 2; pr++)
#pragma unroll
        for (int ti = 0; ti < 2; ti++)
#pragma unroll
            for (int nt = 0; nt < 5; nt++)
#pragma unroll
                for (int r = 0; r < 4; r++) acc[pr][ti][nt][r] = 0.0f;

    for (int tp = 0; tp < TP; tp++) {
#pragma unroll
        for (int ck = 0; ck < 3; ck++) {
            // B fragments once per (tp, ck) — shared by both pair tiles
            const uint32_t* wb = swh2 + (tp * CPAD + ck * 8) * K_OUT;
            uint32_t bb[5][2];
#pragma unroll
            for (int nt = 0; nt < 5; nt++) {
                int col = 8 * nt + lg;
                bb[nt][0] = wb[lt * K_OUT + col];
                bb[nt][1] = wb[(lt + 4) * K_OUT + col];
            }
            // A channel rows: c = ck*8 + lt (a0/a1), +4 (a2/a3)
            const uint32_t* x0 = sxh2 + (ck * 8 + lt) * XROW2;
            const uint32_t* x1 = x0 + 4 * XROW2;
#pragma unroll
            for (int pr = 0; pr < 2; pr++) {
                if (pr == 1 && !has1) break;
#pragma unroll
                for (int ti = 0; ti < 2; ti++) {
                    int o = offA[pr][ti] + tp;
                    uint32_t a0 = x0[o];
                    uint32_t a1 = x0[o + 4];
                    uint32_t a2 = x1[o];
                    uint32_t a3 = x1[o + 4];
#pragma unroll
                    for (int nt = 0; nt < 5; nt++)
                        mma_f16(acc[pr][ti][nt], a0, a1, a2, a3, bb[nt][0], bb[nt][1]);
                }
            }
        }
    }

    // epilogue: bias + ELU + BN stats + pooling, fragment-resident
#pragma unroll
    for (int pr = 0; pr < 2; pr++) {
        if (pr == 1 && !has1) break;
        const int w0 = pr ? w0b : w0a;
        const int p0 = w0 / P_POOL;
#pragma unroll
        for (int nt = 0; nt < 5; nt++) {
#pragma unroll
            for (int rk = 0; rk < 2; rk++) {
                const int k = 8 * nt + 2 * lt + rk;
                const float bk = sbias[k];
                float s1 = 0.f, s2 = 0.f, q0 = 0.f, q1 = 0.f;
#pragma unroll
                for (int ti = 0; ti < 2; ti++) {
#pragma unroll
                    for (int rh = 0; rh < 2; rh++) {
                        int w = w0 + 16 * ti + lg + 8 * rh;
                        float v = acc[pr][ti][nt][2 * rh + rk] + bk;
                        float y = v > 0.0f ? v : (__expf(v) - 1.0f);
                        if (w < W_OUT) {
                            s1 += y;
                            s2 += y * y;
                            if (w < N_POOL * P_POOL) {
                                float pv = y * 0.01f;
                                if (w / P_POOL == p0) q0 += pv; else q1 += pv;
                            }
                        }
                    }
                }
#pragma unroll
                for (int off = 4; off < 32; off <<= 1) {
                    s1 += __shfl_xor_sync(0xffffffffu, s1, off);
                    s2 += __shfl_xor_sync(0xffffffffu, s2, off);
                    q0 += __shfl_xor_sync(0xffffffffu, q0, off);
                    q1 += __shfl_xor_sync(0xffffffffu, q1, off);
                }
                if (lg == 0) {
                    atomicAdd(&sb1[k], s1);
                    atomicAdd(&sb2[k], s2);
                    if (p0 < N_POOL)     atomicAdd(&spool[k * N_POOL + p0], q0);
                    if (p0 + 1 < N_POOL) atomicAdd(&spool[k * N_POOL + p0 + 1], q1);
                }
            }
        }
    }
    __syncthreads();

    float* gp = g_pooled + (size_t)b * FEAT;
    for (int i = tid; i < FEAT; i += NTHR) gp[i] = spool[i];
    if (tid < K_OUT) {
        g_bnpart[(size_t)b * (2 * K_OUT) + tid]         = sb1[tid];
        g_bnpart[(size_t)b * (2 * K_OUT) + K_OUT + tid] = sb2[tid];
    }
}

// ---------------- pass 2: BN stats reduce ----------------
__global__ void bn_reduce_kernel(const float* __restrict__ gamma,
                                 const float* __restrict__ beta) {
    __shared__ float r1[256];
    __shared__ float r2[256];
    int k = blockIdx.x;
    int tid = threadIdx.x;
    float s1 = 0.0f, s2 = 0.0f;
    for (int b = tid; b < B_SIZE; b += 256) {
        s1 += g_bnpart[(size_t)b * (2 * K_OUT) + k];
        s2 += g_bnpart[(size_t)b * (2 * K_OUT) + K_OUT + k];
    }
    r1[tid] = s1; r2[tid] = s2;
    __syncthreads();
    for (int s = 128; s > 0; s >>= 1) {
        if (tid < s) { r1[tid] += r1[tid + s]; r2[tid] += r2[tid + s]; }
        __syncthreads();
    }
    if (tid == 0) {
        const float N = (float)((size_t)B_SIZE * W_OUT);
        float mean = r1[0] / N;
        float var  = r2[0] / N - mean * mean;
        float sc   = gamma[k] * rsqrtf(var + 1e-5f);
        g_scale[k] = sc;
        g_shift[k] = beta[k] - mean * sc;
    }
}

// ---------------- pass 3: subject-gathered FC (warp per sample) ----------------
__global__ void fc_kernel(const float* __restrict__ x,
                          const float* __restrict__ fc_w,
                          const float* __restrict__ fc_b,
                          float* __restrict__ out) {
    int wid  = threadIdx.x >> 5;
    int lane = threadIdx.x & 31;
    int b = blockIdx.x * 8 + wid;
    if (b >= B_SIZE) return;
    int sid = __float2int_rn(x[(size_t)b * (C_CH * T_FULL) + T_IN] * 1e-6f) - 1;
    const float4* Wp = (const float4*)(fc_w + (size_t)sid * FEAT * O_OUT);
    const float*  pf = g_pooled + (size_t)b * FEAT;
    float a0 = 0.f, a1 = 0.f, a2 = 0.f, a3 = 0.f;
#pragma unroll
    for (int j = 0; j < 12; j++) {
        int f = lane + j * 32;
        if (f < FEAT) {
            int k = f / N_POOL;
            float v = pf[f] * g_scale[k] + g_shift[k];
            float4 wv = Wp[f];
            a0 += v * wv.x; a1 += v * wv.y; a2 += v * wv.z; a3 += v * wv.w;
        }
    }
#pragma unroll
    for (int off = 16; off > 0; off >>= 1) {
        a0 += __shfl_xor_sync(0xffffffffu, a0, off);
        a1 += __shfl_xor_sync(0xffffffffu, a1, off);
        a2 += __shfl_xor_sync(0xffffffffu, a2, off);
        a3 += __shfl_xor_sync(0xffffffffu, a3, off);
    }
    if (lane == 0) {
        const float* fb = fc_b + sid * O_OUT;
        float4 o = make_float4(a0 + fb[0], a1 + fb[1], a2 + fb[2], a3 + fb[3]);
        ((float4*)out)[b] = o;
    }
}

// ---------------- launch ----------------
extern "C" void kernel_launch(void* const* d_in, const int* in_sizes, int n_in,
                              void* d_out, int out_size) {
    const float* x      = (const float*)d_in[0];
    const float* conv_w = (const float*)d_in[1];
    const float* conv_b = (const float*)d_in[2];
    const float* gamma  = (const float*)d_in[3];
    const float* beta   = (const float*)d_in[4];
    const float* fc_w   = (const float*)d_in[5];
    const float* fc_b   = (const float*)d_in[6];
    float* out = (float*)d_out;

    cudaFuncSetAttribute(conv_mma_kernel,
                         cudaFuncAttributeMaxDynamicSharedMemorySize, SMEM_BYTES);

    prep_w_kernel<<<(SWH2 + 255) / 256, 256>>>(conv_w);
    conv_mma_kernel<<<B_SIZE, NTHR, SMEM_BYTES>>>(x, conv_b);
    bn_reduce_kernel<<<K_OUT, 256>>>(gamma, beta);
    fc_kernel<<<B_SIZE / 8, 256>>>(x, fc_w, fc_b, out);
}

// round 12
// speedup vs baseline: 4.6836x; 1.0764x over previous
#include <cuda_runtime.h>
#include <cuda_fp16.h>
#include <cstdint>

// ---------------- problem constants ----------------
#define B_SIZE 4096
#define C_CH   22
#define T_FULL 1002
#define T_IN   1001
#define K_OUT  40
#define KSZ    25
#define W_OUT  977
#define P_POOL 100
#define N_POOL 9
#define FEAT   360
#define O_OUT  4

// ---------------- tiling ----------------
#define TP     13                 // tap pairs (25 taps, last padded)
#define CPAD   24                 // channels padded 22 -> 24 (3 chunks of 8)
#define XP2    276                // half2 per phase array (276 mod 32 = 20)
#define XROW2  (2*XP2)            // half2 per channel row (552, mod 32 = 8)
#define SXH2   (CPAD*XROW2)       // 13248 half2
#define SWH2   (TP*CPAD*K_OUT)    // 12480 half2
#define NTHR   512
#define NWARP  16

// smem byte offsets
#define SM_X     0
#define SM_W     (SXH2*4)                  // 52992
#define SM_POOL  (SM_W + SWH2*4)           // 102912
#define SM_B1    (SM_POOL + FEAT*4)        // 104352
#define SM_B2    (SM_B1 + K_OUT*4)         // 104512
#define SM_BIAS  (SM_B2 + K_OUT*4)         // 104672
#define SMEM_BYTES (SM_BIAS + K_OUT*4)     // 104832  -> 2 CTAs/SM

// ---------------- device scratch ----------------
__device__ uint32_t g_wh2[SWH2];                       // [tp][c24][k40] half2 = (w[t0], w[t0+1])
__device__ float g_pooled[(size_t)B_SIZE * FEAT];
__device__ float g_bnpart[(size_t)2 * B_SIZE * 2 * K_OUT];  // [bx(8192)][2][40]
__device__ float g_scale[K_OUT];
__device__ float g_shift[K_OUT];

// ---------------- helpers ----------------
__device__ __forceinline__ void mma_f16(float* d,
                                        uint32_t a0, uint32_t a1, uint32_t a2, uint32_t a3,
                                        uint32_t b0, uint32_t b1) {
    asm volatile(
        "mma.sync.aligned.m16n8k16.row.col.f32.f16.f16.f32 "
        "{%0,%1,%2,%3}, {%4,%5,%6,%7}, {%8,%9}, {%0,%1,%2,%3};"
        : "+f"(d[0]), "+f"(d[1]), "+f"(d[2]), "+f"(d[3])
        : "r"(a0), "r"(a1), "r"(a2), "r"(a3), "r"(b0), "r"(b1));
}

// ---------------- pass 0: weights -> [tp][c24][k40] tap-pair half2 ----------------
__global__ void prep_w_kernel(const float* __restrict__ cw) {
    int idx = blockIdx.x * blockDim.x + threadIdx.x;
    if (idx >= SWH2) return;
    int tp  = idx / (CPAD * K_OUT);
    int rem = idx - tp * (CPAD * K_OUT);
    int c   = rem / K_OUT;
    int k   = rem - c * K_OUT;
    int t0 = 2 * tp, t1 = 2 * tp + 1;
    float v0 = (c < C_CH) ? cw[(k * C_CH + c) * KSZ + t0] : 0.0f;
    float v1 = (c < C_CH && t1 < KSZ) ? cw[(k * C_CH + c) * KSZ + t1] : 0.0f;
    half2 h = __floats2half2_rn(v0, v1);
    g_wh2[idx] = *(uint32_t*)&h;
}

// ---------------- pass 1: f16 mma conv + ELU + pool + BN partials ----------------
// grid = 2*B : bx = b*2 + half.  half0: w in [0,500) bins 0-4 (16 tiles),
//                               half1: w in [500,977) bins 5-8 (15 tiles)
__global__ void __launch_bounds__(NTHR, 2)
conv_mma_kernel(const float* __restrict__ x, const float* __restrict__ bias) {
    extern __shared__ char smemc[];
    uint32_t* sxh2  = (uint32_t*)(smemc + SM_X);
    uint32_t* swh2  = (uint32_t*)(smemc + SM_W);
    float*    spool = (float*)(smemc + SM_POOL);
    float*    sb1   = (float*)(smemc + SM_B1);
    float*    sb2   = (float*)(smemc + SM_B2);
    float*    sbias = (float*)(smemc + SM_BIAS);

    const int tid  = threadIdx.x;
    const int wid  = tid >> 5;        // 0..15
    const int lane = tid & 31;
    const int lg   = lane >> 2;       // group id (w row)
    const int lt   = lane & 3;        // thread-in-group
    const int bx   = blockIdx.x;
    const int b    = bx >> 1;
    const int half = bx & 1;

    const int wbase  = half ? 500 : 0;       // even -> phase parity = lg&1
    const int ntile  = half ? 15 : 16;
    const int whi    = half ? W_OUT : 500;

    // stage x window as two phase-shifted half2 arrays per channel:
    //   phase0[c][j] = (x[wbase+2j],   x[wbase+2j+1])
    //   phase1[c][j] = (x[wbase+2j+1], x[wbase+2j+2])
    const float* xg = x + (size_t)b * (C_CH * T_FULL);
    for (int i = tid; i < SXH2; i += NTHR) {
        int c   = i / XROW2;
        int rem = i - c * XROW2;
        int ph  = rem >= XP2;
        int j   = rem - ph * XP2;
        int wg  = wbase + 2 * j + ph;
        float v0 = (c < C_CH && wg < T_IN) ? xg[c * T_FULL + wg] : 0.0f;
        float v1 = (c < C_CH && wg + 1 < T_IN) ? xg[c * T_FULL + wg + 1] : 0.0f;
        half2 h = __floats2half2_rn(v0, v1);
        sxh2[i] = *(uint32_t*)&h;
    }
    for (int i = tid; i < SWH2; i += NTHR) swh2[i] = g_wh2[i];
    for (int i = tid; i < FEAT + 2 * K_OUT; i += NTHR) spool[i] = 0.0f;
    if (tid < K_OUT) sbias[tid] = bias[tid];
    __syncthreads();

    if (wid < ntile) {
        const int w0 = wbase + wid * 32;     // global tile start
        // per-thread A offsets (local coords): off = (wloc>>1) + (lg&1)*XP2
        const int phoff = (lg & 1) * XP2;
        const int offA0 = 16 * wid + (lg >> 1) + phoff;   // ti=0; ti=1 adds 8

        float acc[2][5][4];
#pragma unroll
        for (int ti = 0; ti < 2; ti++)
#pragma unroll
            for (int nt = 0; nt < 5; nt++)
#pragma unroll
                for (int r = 0; r < 4; r++) acc[ti][nt][r] = 0.0f;

        for (int tp = 0; tp < TP; tp++) {
#pragma unroll
            for (int ck = 0; ck < 3; ck++) {
                const uint32_t* wb = swh2 + (tp * CPAD + ck * 8) * K_OUT;
                uint32_t bb[5][2];
#pragma unroll
                for (int nt = 0; nt < 5; nt++) {
                    int col = 8 * nt + lg;
                    bb[nt][0] = wb[lt * K_OUT + col];
                    bb[nt][1] = wb[(lt + 4) * K_OUT + col];
                }
                const uint32_t* x0 = sxh2 + (ck * 8 + lt) * XROW2;
                const uint32_t* x1 = x0 + 4 * XROW2;
#pragma unroll
                for (int ti = 0; ti < 2; ti++) {
                    int o = offA0 + 8 * ti + tp;
                    uint32_t a0 = x0[o];
                    uint32_t a1 = x0[o + 4];
                    uint32_t a2 = x1[o];
                    uint32_t a3 = x1[o + 4];
#pragma unroll
                    for (int nt = 0; nt < 5; nt++)
                        mma_f16(acc[ti][nt], a0, a1, a2, a3, bb[nt][0], bb[nt][1]);
                }
            }
        }

        // epilogue: bias + ELU + BN stats + pooling, fragment-resident
        const int p0 = w0 / P_POOL;
#pragma unroll
        for (int nt = 0; nt < 5; nt++) {
#pragma unroll
            for (int rk = 0; rk < 2; rk++) {
                const int k = 8 * nt + 2 * lt + rk;
                const float bk = sbias[k];
                float s1 = 0.f, s2 = 0.f, q0 = 0.f, q1 = 0.f;
#pragma unroll
                for (int ti = 0; ti < 2; ti++) {
#pragma unroll
                    for (int rh = 0; rh < 2; rh++) {
                        int w = w0 + 16 * ti + lg + 8 * rh;
                        float v = acc[ti][nt][2 * rh + rk] + bk;
                        float y = v > 0.0f ? v : (__expf(v) - 1.0f);
                        if (w < whi) {           // [wbase, whi) partition of BN range
                            s1 += y;
                            s2 += y * y;
                            if (w < N_POOL * P_POOL) {
                                float pv = y * 0.01f;
                                if (w / P_POOL == p0) q0 += pv; else q1 += pv;
                            }
                        }
                    }
                }
#pragma unroll
                for (int off = 4; off < 32; off <<= 1) {
                    s1 += __shfl_xor_sync(0xffffffffu, s1, off);
                    s2 += __shfl_xor_sync(0xffffffffu, s2, off);
                    q0 += __shfl_xor_sync(0xffffffffu, q0, off);
                    q1 += __shfl_xor_sync(0xffffffffu, q1, off);
                }
                if (lg == 0) {
                    atomicAdd(&sb1[k], s1);
                    atomicAdd(&sb2[k], s2);
                    if (p0 < N_POOL)     atomicAdd(&spool[k * N_POOL + p0], q0);
                    if (p0 + 1 < N_POOL) atomicAdd(&spool[k * N_POOL + p0 + 1], q1);
                }
            }
        }
    }
    __syncthreads();

    // write only this half's pool bins (disjoint across the two CTAs of b)
    float* gp = g_pooled + (size_t)b * FEAT;
    for (int i = tid; i < FEAT; i += NTHR) {
        int n = i - (i / N_POOL) * N_POOL;
        bool mine = half ? (n >= 5) : (n < 5);
        if (mine) gp[i] = spool[i];
    }
    if (tid < K_OUT) {
        g_bnpart[(size_t)bx * (2 * K_OUT) + tid]         = sb1[tid];
        g_bnpart[(size_t)bx * (2 * K_OUT) + K_OUT + tid] = sb2[tid];
    }
}

// ---------------- pass 2: BN stats reduce (over 2B partials) ----------------
__global__ void bn_reduce_kernel(const float* __restrict__ gamma,
                                 const float* __restrict__ beta) {
    __shared__ float r1[256];
    __shared__ float r2[256];
    int k = blockIdx.x;
    int tid = threadIdx.x;
    float s1 = 0.0f, s2 = 0.0f;
    for (int bx = tid; bx < 2 * B_SIZE; bx += 256) {
        s1 += g_bnpart[(size_t)bx * (2 * K_OUT) + k];
        s2 += g_bnpart[(size_t)bx * (2 * K_OUT) + K_OUT + k];
    }
    r1[tid] = s1; r2[tid] = s2;
    __syncthreads();
    for (int s = 128; s > 0; s >>= 1) {
        if (tid < s) { r1[tid] += r1[tid + s]; r2[tid] += r2[tid + s]; }
        __syncthreads();
    }
    if (tid == 0) {
        const float N = (float)((size_t)B_SIZE * W_OUT);
        float mean = r1[0] / N;
        float var  = r2[0] / N - mean * mean;
        float sc   = gamma[k] * rsqrtf(var + 1e-5f);
        g_scale[k] = sc;
        g_shift[k] = beta[k] - mean * sc;
    }
}

// ---------------- pass 3: subject-gathered FC (warp per sample) ----------------
__global__ void fc_kernel(const float* __restrict__ x,
                          const float* __restrict__ fc_w,
                          const float* __restrict__ fc_b,
                          float* __restrict__ out) {
    int wid  = threadIdx.x >> 5;
    int lane = threadIdx.x & 31;
    int b = blockIdx.x * 8 + wid;
    if (b >= B_SIZE) return;
    int sid = __float2int_rn(x[(size_t)b * (C_CH * T_FULL) + T_IN] * 1e-6f) - 1;
    const float4* Wp = (const float4*)(fc_w + (size_t)sid * FEAT * O_OUT);
    const float*  pf = g_pooled + (size_t)b * FEAT;
    float a0 = 0.f, a1 = 0.f, a2 = 0.f, a3 = 0.f;
#pragma unroll
    for (int j = 0; j < 12; j++) {
        int f = lane + j * 32;
        if (f < FEAT) {
            int k = f / N_POOL;
            float v = pf[f] * g_scale[k] + g_shift[k];
            float4 wv = Wp[f];
            a0 += v * wv.x; a1 += v * wv.y; a2 += v * wv.z; a3 += v * wv.w;
        }
    }
#pragma unroll
    for (int off = 16; off > 0; off >>= 1) {
        a0 += __shfl_xor_sync(0xffffffffu, a0, off);
        a1 += __shfl_xor_sync(0xffffffffu, a1, off);
        a2 += __shfl_xor_sync(0xffffffffu, a2, off);
        a3 += __shfl_xor_sync(0xffffffffu, a3, off);
    }
    if (lane == 0) {
        const float* fb = fc_b + sid * O_OUT;
        float4 o = make_float4(a0 + fb[0], a1 + fb[1], a2 + fb[2], a3 + fb[3]);
        ((float4*)out)[b] = o;
    }
}

// ---------------- launch ----------------
extern "C" void kernel_launch(void* const* d_in, const int* in_sizes, int n_in,
                              void* d_out, int out_size) {
    const float* x      = (const float*)d_in[0];
    const float* conv_w = (const float*)d_in[1];
    const float* conv_b = (const float*)d_in[2];
    const float* gamma  = (const float*)d_in[3];
    const float* beta   = (const float*)d_in[4];
    const float* fc_w   = (const float*)d_in[5];
    const float* fc_b   = (const float*)d_in[6];
    float* out = (float*)d_out;

    cudaFuncSetAttribute(conv_mma_kernel,
                         cudaFuncAttributeMaxDynamicSharedMemorySize, SMEM_BYTES);

    prep_w_kernel<<<(SWH2 + 255) / 256, 256>>>(conv_w);
    conv_mma_kernel<<<2 * B_SIZE, NTHR, SMEM_BYTES>>>(x, conv_b);
    bn_reduce_kernel<<<K_OUT, 256>>>(gamma, beta);
    fc_kernel<<<B_SIZE / 8, 256>>>(x, fc_w, fc_b, out);
}

// round 13
// speedup vs baseline: 4.8195x; 1.0290x over previous
#include <cuda_runtime.h>
#include <cuda_fp16.h>
#include <cstdint>

// ---------------- problem constants ----------------
#define B_SIZE 4096
#define C_CH   22
#define T_FULL 1002
#define T_IN   1001
#define K_OUT  40
#define KSZ    25
#define W_OUT  977
#define P_POOL 100
#define N_POOL 9
#define FEAT   360
#define O_OUT  4

// ---------------- tiling ----------------
#define TP     13                 // tap pairs (25 taps, last padded)
#define CPAD   24                 // channels padded 22 -> 24 (3 chunks of 8)
#define XP2    276                // half2 per phase array
#define XROW2  (2*XP2)            // half2 per channel row (552, mod 32 = 8)
#define SXH2   (CPAD*XROW2)       // 13248 half2
#define SWH2   (TP*CPAD*K_OUT)    // 12480 half2
#define NTHR   512
#define NCTA   304                // 2 CTAs x 152 SMs, persistent
#define NITEM  (2*B_SIZE)         // (b, half) work items

// smem byte offsets
#define SM_X     0
#define SM_W     (SXH2*4)                  // 52992
#define SM_POOL  (SM_W + SWH2*4)           // 102912
#define SM_B1    (SM_POOL + FEAT*4)        // 104352
#define SM_B2    (SM_B1 + K_OUT*4)         // 104512
#define SM_BIAS  (SM_B2 + K_OUT*4)         // 104672
#define SMEM_BYTES (SM_BIAS + K_OUT*4)     // 104832  -> 2 CTAs/SM

// ---------------- device scratch ----------------
__device__ uint32_t g_wh2[SWH2];                       // [tp][c24][k40] half2 = (w[t0], w[t0+1])
__device__ float g_pooled[(size_t)B_SIZE * FEAT];
__device__ float g_bnpart[(size_t)NITEM * 2 * K_OUT];
__device__ float g_scale[K_OUT];
__device__ float g_shift[K_OUT];

// ---------------- helpers ----------------
__device__ __forceinline__ void mma_f16(float* d,
                                        uint32_t a0, uint32_t a1, uint32_t a2, uint32_t a3,
                                        uint32_t b0, uint32_t b1) {
    asm volatile(
        "mma.sync.aligned.m16n8k16.row.col.f32.f16.f16.f32 "
        "{%0,%1,%2,%3}, {%4,%5,%6,%7}, {%8,%9}, {%0,%1,%2,%3};"
        : "+f"(d[0]), "+f"(d[1]), "+f"(d[2]), "+f"(d[3])
        : "r"(a0), "r"(a1), "r"(a2), "r"(a3), "r"(b0), "r"(b1));
}

// ---------------- pass 0: weights -> [tp][c24][k40] tap-pair half2 ----------------
__global__ void prep_w_kernel(const float* __restrict__ cw) {
    int idx = blockIdx.x * blockDim.x + threadIdx.x;
    if (idx >= SWH2) return;
    int tp  = idx / (CPAD * K_OUT);
    int rem = idx - tp * (CPAD * K_OUT);
    int c   = rem / K_OUT;
    int k   = rem - c * K_OUT;
    int t0 = 2 * tp, t1 = 2 * tp + 1;
    float v0 = (c < C_CH) ? cw[(k * C_CH + c) * KSZ + t0] : 0.0f;
    float v1 = (c < C_CH && t1 < KSZ) ? cw[(k * C_CH + c) * KSZ + t1] : 0.0f;
    half2 h = __floats2half2_rn(v0, v1);
    g_wh2[idx] = *(uint32_t*)&h;
}

// ---------------- pass 1: persistent f16 mma conv + ELU + pool + BN partials ----------------
// items bx = b*2 + half.  half0: w in [0,500) bins 0-4 (16 tiles),
//                         half1: w in [500,977) bins 5-8 (15 tiles)
__global__ void __launch_bounds__(NTHR, 2)
conv_mma_kernel(const float* __restrict__ x, const float* __restrict__ bias) {
    extern __shared__ char smemc[];
    uint32_t* sxh2  = (uint32_t*)(smemc + SM_X);
    uint32_t* swh2  = (uint32_t*)(smemc + SM_W);
    float*    spool = (float*)(smemc + SM_POOL);
    float*    sb1   = (float*)(smemc + SM_B1);
    float*    sb2   = (float*)(smemc + SM_B2);
    float*    sbias = (float*)(smemc + SM_BIAS);

    const int tid  = threadIdx.x;
    const int wid  = tid >> 5;        // 0..15
    const int lane = tid & 31;
    const int lg   = lane >> 2;       // group id (w row)
    const int lt   = lane & 3;        // thread-in-group

    // stage weights + bias ONCE per persistent CTA
    for (int i = tid; i < SWH2; i += NTHR) swh2[i] = g_wh2[i];
    if (tid < K_OUT) sbias[tid] = bias[tid];

    const int phoff = (lg & 1) * XP2;

    for (int bx = blockIdx.x; bx < NITEM; bx += NCTA) {
        const int b    = bx >> 1;
        const int half = bx & 1;
        const int wbase = half ? 500 : 0;
        const int ntile = half ? 15 : 16;
        const int whi   = half ? W_OUT : 500;

        __syncthreads();   // prev item's spool reads / x reads complete

        // stage x window as two phase-shifted half2 arrays per channel
        const float* xg = x + (size_t)b * (C_CH * T_FULL);
        for (int i = tid; i < SXH2; i += NTHR) {
            int c   = i / XROW2;
            int rem = i - c * XROW2;
            int ph  = rem >= XP2;
            int j   = rem - ph * XP2;
            int wg  = wbase + 2 * j + ph;
            float v0 = (c < C_CH && wg < T_IN) ? xg[c * T_FULL + wg] : 0.0f;
            float v1 = (c < C_CH && wg + 1 < T_IN) ? xg[c * T_FULL + wg + 1] : 0.0f;
            half2 h = __floats2half2_rn(v0, v1);
            sxh2[i] = *(uint32_t*)&h;
        }
        for (int i = tid; i < FEAT + 2 * K_OUT; i += NTHR) spool[i] = 0.0f;
        __syncthreads();

        if (wid < ntile) {
            const int w0 = wbase + wid * 32;
            const int offA0 = 16 * wid + (lg >> 1) + phoff;

            float acc[2][5][4];
#pragma unroll
            for (int ti = 0; ti < 2; ti++)
#pragma unroll
                for (int nt = 0; nt < 5; nt++)
#pragma unroll
                    for (int r = 0; r < 4; r++) acc[ti][nt][r] = 0.0f;

            for (int tp = 0; tp < TP; tp++) {
#pragma unroll
                for (int ck = 0; ck < 3; ck++) {
                    const uint32_t* wb = swh2 + (tp * CPAD + ck * 8) * K_OUT;
                    uint32_t bb[5][2];
#pragma unroll
                    for (int nt = 0; nt < 5; nt++) {
                        int col = 8 * nt + lg;
                        bb[nt][0] = wb[lt * K_OUT + col];
                        bb[nt][1] = wb[(lt + 4) * K_OUT + col];
                    }
                    const uint32_t* x0 = sxh2 + (ck * 8 + lt) * XROW2;
                    const uint32_t* x1 = x0 + 4 * XROW2;
#pragma unroll
                    for (int ti = 0; ti < 2; ti++) {
                        int o = offA0 + 8 * ti + tp;
                        uint32_t a0 = x0[o];
                        uint32_t a1 = x0[o + 4];
                        uint32_t a2 = x1[o];
                        uint32_t a3 = x1[o + 4];
#pragma unroll
                        for (int nt = 0; nt < 5; nt++)
                            mma_f16(acc[ti][nt], a0, a1, a2, a3, bb[nt][0], bb[nt][1]);
                    }
                }
            }

            // epilogue: bias + ELU + BN stats + pooling, fragment-resident
            const int p0 = w0 / P_POOL;
#pragma unroll
            for (int nt = 0; nt < 5; nt++) {
#pragma unroll
                for (int rk = 0; rk < 2; rk++) {
                    const int k = 8 * nt + 2 * lt + rk;
                    const float bk = sbias[k];
                    float s1 = 0.f, s2 = 0.f, q0 = 0.f, q1 = 0.f;
#pragma unroll
                    for (int ti = 0; ti < 2; ti++) {
#pragma unroll
                        for (int rh = 0; rh < 2; rh++) {
                            int w = w0 + 16 * ti + lg + 8 * rh;
                            float v = acc[ti][nt][2 * rh + rk] + bk;
                            float y = v > 0.0f ? v : (__expf(v) - 1.0f);
                            if (w < whi) {
                                s1 += y;
                                s2 += y * y;
                                if (w < N_POOL * P_POOL) {
                                    float pv = y * 0.01f;
                                    if (w / P_POOL == p0) q0 += pv; else q1 += pv;
                                }
                            }
                        }
                    }
#pragma unroll
                    for (int off = 4; off < 32; off <<= 1) {
                        s1 += __shfl_xor_sync(0xffffffffu, s1, off);
                        s2 += __shfl_xor_sync(0xffffffffu, s2, off);
                        q0 += __shfl_xor_sync(0xffffffffu, q0, off);
                        q1 += __shfl_xor_sync(0xffffffffu, q1, off);
                    }
                    if (lg == 0) {
                        atomicAdd(&sb1[k], s1);
                        atomicAdd(&sb2[k], s2);
                        if (p0 < N_POOL)     atomicAdd(&spool[k * N_POOL + p0], q0);
                        if (p0 + 1 < N_POOL) atomicAdd(&spool[k * N_POOL + p0 + 1], q1);
                    }
                }
            }
        }
        __syncthreads();

        // write only this half's pool bins (disjoint across the two halves of b)
        float* gp = g_pooled + (size_t)b * FEAT;
        for (int i = tid; i < FEAT; i += NTHR) {
            int n = i - (i / N_POOL) * N_POOL;
            bool mine = half ? (n >= 5) : (n < 5);
            if (mine) gp[i] = spool[i];
        }
        if (tid < K_OUT) {
            g_bnpart[(size_t)bx * (2 * K_OUT) + tid]         = sb1[tid];
            g_bnpart[(size_t)bx * (2 * K_OUT) + K_OUT + tid] = sb2[tid];
        }
    }
}

// ---------------- pass 2: BN stats reduce (over 2B partials) ----------------
__global__ void bn_reduce_kernel(const float* __restrict__ gamma,
                                 const float* __restrict__ beta) {
    __shared__ float r1[256];
    __shared__ float r2[256];
    int k = blockIdx.x;
    int tid = threadIdx.x;
    float s1 = 0.0f, s2 = 0.0f;
    for (int bx = tid; bx < NITEM; bx += 256) {
        s1 += g_bnpart[(size_t)bx * (2 * K_OUT) + k];
        s2 += g_bnpart[(size_t)bx * (2 * K_OUT) + K_OUT + k];
    }
    r1[tid] = s1; r2[tid] = s2;
    __syncthreads();
    for (int s = 128; s > 0; s >>= 1) {
        if (tid < s) { r1[tid] += r1[tid + s]; r2[tid] += r2[tid + s]; }
        __syncthreads();
    }
    if (tid == 0) {
        const float N = (float)((size_t)B_SIZE * W_OUT);
        float mean = r1[0] / N;
        float var  = r2[0] / N - mean * mean;
        float sc   = gamma[k] * rsqrtf(var + 1e-5f);
        g_scale[k] = sc;
        g_shift[k] = beta[k] - mean * sc;
    }
}

// ---------------- pass 3: subject-gathered FC (warp per sample) ----------------
__global__ void fc_kernel(const float* __restrict__ x,
                          const float* __restrict__ fc_w,
                          const float* __restrict__ fc_b,
                          float* __restrict__ out) {
    int wid  = threadIdx.x >> 5;
    int lane = threadIdx.x & 31;
    int b = blockIdx.x * 8 + wid;
    if (b >= B_SIZE) return;
    int sid = __float2int_rn(x[(size_t)b * (C_CH * T_FULL) + T_IN] * 1e-6f) - 1;
    const float4* Wp = (const float4*)(fc_w + (size_t)sid * FEAT * O_OUT);
    const float*  pf = g_pooled + (size_t)b * FEAT;
    float a0 = 0.f, a1 = 0.f, a2 = 0.f, a3 = 0.f;
#pragma unroll
    for (int j = 0; j < 12; j++) {
        int f = lane + j * 32;
        if (f < FEAT) {
            int k = f / N_POOL;
            float v = pf[f] * g_scale[k] + g_shift[k];
            float4 wv = Wp[f];
            a0 += v * wv.x; a1 += v * wv.y; a2 += v * wv.z; a3 += v * wv.w;
        }
    }
#pragma unroll
    for (int off = 16; off > 0; off >>= 1) {
        a0 += __shfl_xor_sync(0xffffffffu, a0, off);
        a1 += __shfl_xor_sync(0xffffffffu, a1, off);
        a2 += __shfl_xor_sync(0xffffffffu, a2, off);
        a3 += __shfl_xor_sync(0xffffffffu, a3, off);
    }
    if (lane == 0) {
        const float* fb = fc_b + sid * O_OUT;
        float4 o = make_float4(a0 + fb[0], a1 + fb[1], a2 + fb[2], a3 + fb[3]);
        ((float4*)out)[b] = o;
    }
}

// ---------------- launch ----------------
extern "C" void kernel_launch(void* const* d_in, const int* in_sizes, int n_in,
                              void* d_out, int out_size) {
    const float* x      = (const float*)d_in[0];
    const float* conv_w = (const float*)d_in[1];
    const float* conv_b = (const float*)d_in[2];
    const float* gamma  = (const float*)d_in[3];
    const float* beta   = (const float*)d_in[4];
    const float* fc_w   = (const float*)d_in[5];
    const float* fc_b   = (const float*)d_in[6];
    float* out = (float*)d_out;

    cudaFuncSetAttribute(conv_mma_kernel,
                         cudaFuncAttributeMaxDynamicSharedMemorySize, SMEM_BYTES);

    prep_w_kernel<<<(SWH2 + 255) / 256, 256>>>(conv_w);
    conv_mma_kernel<<<NCTA, NTHR, SMEM_BYTES>>>(x, conv_b);
    bn_reduce_kernel<<<K_OUT, 256>>>(gamma, beta);
    fc_kernel<<<B_SIZE / 8, 256>>>(x, fc_w, fc_b, out);
}

// round 14
// speedup vs baseline: 5.2885x; 1.0973x over previous
#include <cuda_runtime.h>
#include <cuda_fp16.h>
#include <cstdint>

// ---------------- problem constants ----------------
#define B_SIZE 4096
#define C_CH   22
#define T_FULL 1002
#define T_IN   1001
#define K_OUT  40
#define KSZ    25
#define W_OUT  977
#define P_POOL 100
#define N_POOL 9
#define FEAT   360
#define O_OUT  4

// ---------------- tiling ----------------
#define NCP    11                 // channel pairs (22 channels exactly)
#define NROWX  12                 // 11 real rows + 1 zero row for pad slots
#define XROWH  536                // h2 per row: 512 tile span + 24 halo (536 mod 32 = 24)
#define SXH2   (NROWX*XROWH)      // 6432 half2
#define NSLOT  275                // real (cp, t) K-pair slots
#define NSLOTP 280                // padded to 35 chunks of 8
#define NCHUNK 35
#define SWH2   (NSLOTP*K_OUT)     // 11200 half2
#define NTHR   512
#define NCTA   304                // 2 CTAs x 152 SMs, persistent
#define NITEM  (2*B_SIZE)         // (b, half) work items

// smem byte offsets
#define SM_X     0
#define SM_W     (SXH2*4)                  // 25728
#define SM_TBL   (SM_W + SWH2*4)           // 70528
#define SM_POOL  (SM_TBL + NSLOTP*4)       // 71648
#define SM_B1    (SM_POOL + FEAT*4)        // 73088
#define SM_B2    (SM_B1 + K_OUT*4)         // 73248
#define SM_BIAS  (SM_B2 + K_OUT*4)         // 73408
#define SMEM_BYTES (SM_BIAS + K_OUT*4)     // 73568 -> 2 CTAs/SM

// ---------------- device scratch ----------------
__device__ uint32_t g_wh2[SWH2];                       // [slot280][k40] half2 = (w[k][c0][t], w[k][c1][t])
__device__ float g_pooled[(size_t)B_SIZE * FEAT];
__device__ float g_bnpart[(size_t)NITEM * 2 * K_OUT];
__device__ float g_scale[K_OUT];
__device__ float g_shift[K_OUT];

// ---------------- helpers ----------------
__device__ __forceinline__ void mma_f16(float* d,
                                        uint32_t a0, uint32_t a1, uint32_t a2, uint32_t a3,
                                        uint32_t b0, uint32_t b1) {
    asm volatile(
        "mma.sync.aligned.m16n8k16.row.col.f32.f16.f16.f32 "
        "{%0,%1,%2,%3}, {%4,%5,%6,%7}, {%8,%9}, {%0,%1,%2,%3};"
        : "+f"(d[0]), "+f"(d[1]), "+f"(d[2]), "+f"(d[3])
        : "r"(a0), "r"(a1), "r"(a2), "r"(a3), "r"(b0), "r"(b1));
}

// slot -> (cp, t):  t = slot / 11, cp = slot % 11   (slot < 275)
// ---------------- pass 0: weights -> [slot][k40] channel-pair half2 ----------------
__global__ void prep_w_kernel(const float* __restrict__ cw) {
    int idx = blockIdx.x * blockDim.x + threadIdx.x;
    if (idx >= SWH2) return;
    int slot = idx / K_OUT;
    int k    = idx - slot * K_OUT;
    float v0 = 0.0f, v1 = 0.0f;
    if (slot < NSLOT) {
        int t  = slot / NCP;
        int cp = slot - t * NCP;
        v0 = cw[(k * C_CH + 2 * cp) * KSZ + t];
        v1 = cw[(k * C_CH + 2 * cp + 1) * KSZ + t];
    }
    half2 h = __floats2half2_rn(v0, v1);
    g_wh2[idx] = *(uint32_t*)&h;
}

// ---------------- pass 1: persistent f16 mma conv + ELU + pool + BN partials ----------------
// items bx = b*2 + half.  half0: w in [0,500) bins 0-4 (16 tiles),
//                         half1: w in [500,977) bins 5-8 (15 tiles)
__global__ void __launch_bounds__(NTHR, 2)
conv_mma_kernel(const float* __restrict__ x, const float* __restrict__ bias) {
    extern __shared__ char smemc[];
    uint32_t* sxh2  = (uint32_t*)(smemc + SM_X);
    uint32_t* swh2  = (uint32_t*)(smemc + SM_W);
    int*      stbl  = (int*)(smemc + SM_TBL);
    float*    spool = (float*)(smemc + SM_POOL);
    float*    sb1   = (float*)(smemc + SM_B1);
    float*    sb2   = (float*)(smemc + SM_B2);
    float*    sbias = (float*)(smemc + SM_BIAS);

    const int tid  = threadIdx.x;
    const int wid  = tid >> 5;        // 0..15
    const int lane = tid & 31;
    const int lg   = lane >> 2;       // group id (w row)
    const int lt   = lane & 3;        // thread-in-group

    // stage weights + slot table + bias ONCE per persistent CTA
    for (int i = tid; i < SWH2; i += NTHR) swh2[i] = g_wh2[i];
    for (int i = tid; i < NSLOTP; i += NTHR) {
        int off;
        if (i < NSLOT) {
            int t  = i / NCP;
            int cp = i - t * NCP;
            off = cp * XROWH + t;
        } else {
            off = NCP * XROWH;       // zero row
        }
        stbl[i] = off;
    }
    if (tid < K_OUT) sbias[tid] = bias[tid];

    for (int bx = blockIdx.x; bx < NITEM; bx += NCTA) {
        const int b    = bx >> 1;
        const int half = bx & 1;
        const int wbase = half ? 500 : 0;
        const int ntile = half ? 15 : 16;
        const int whi   = half ? W_OUT : 500;

        __syncthreads();   // prev item's smem reads complete

        // stage x window: row cp holds half2 (x[2cp][w], x[2cp+1][w]), w = wbase + wloc
        const float* xg = x + (size_t)b * (C_CH * T_FULL);
        for (int i = tid; i < SXH2; i += NTHR) {
            int cp   = i / XROWH;
            int wloc = i - cp * XROWH;
            int wg   = wbase + wloc;
            float v0 = 0.0f, v1 = 0.0f;
            if (cp < NCP && wg < T_IN) {
                v0 = xg[(2 * cp) * T_FULL + wg];
                v1 = xg[(2 * cp + 1) * T_FULL + wg];
            }
            half2 h = __floats2half2_rn(v0, v1);
            sxh2[i] = *(uint32_t*)&h;
        }
        for (int i = tid; i < FEAT + 2 * K_OUT; i += NTHR) spool[i] = 0.0f;
        __syncthreads();

        if (wid < ntile) {
            const int w0  = wbase + wid * 32;   // global tile start
            const int owl = 32 * wid + lg;      // local w for ti=0 (ti=1: +16)

            float acc[2][5][4];
#pragma unroll
            for (int ti = 0; ti < 2; ti++)
#pragma unroll
                for (int nt = 0; nt < 5; nt++)
#pragma unroll
                    for (int r = 0; r < 4; r++) acc[ti][nt][r] = 0.0f;

            for (int ch = 0; ch < NCHUNK; ch++) {
                const uint32_t* wb = swh2 + ch * 8 * K_OUT;
                uint32_t bb[5][2];
#pragma unroll
                for (int nt = 0; nt < 5; nt++) {
                    int col = 8 * nt + lg;
                    bb[nt][0] = wb[lt * K_OUT + col];
                    bb[nt][1] = wb[(lt + 4) * K_OUT + col];
                }
                const int tb0 = stbl[ch * 8 + lt];
                const int tb2 = stbl[ch * 8 + lt + 4];
#pragma unroll
                for (int ti = 0; ti < 2; ti++) {
                    int o = owl + 16 * ti;
                    uint32_t a0 = sxh2[tb0 + o];
                    uint32_t a1 = sxh2[tb0 + o + 8];
                    uint32_t a2 = sxh2[tb2 + o];
                    uint32_t a3 = sxh2[tb2 + o + 8];
#pragma unroll
                    for (int nt = 0; nt < 5; nt++)
                        mma_f16(acc[ti][nt], a0, a1, a2, a3, bb[nt][0], bb[nt][1]);
                }
            }

            // epilogue: bias + ELU + BN stats + pooling, fragment-resident
            const int p0 = w0 / P_POOL;
#pragma unroll
            for (int nt = 0; nt < 5; nt++) {
#pragma unroll
                for (int rk = 0; rk < 2; rk++) {
                    const int k = 8 * nt + 2 * lt + rk;
                    const float bk = sbias[k];
                    float s1 = 0.f, s2 = 0.f, q0 = 0.f, q1 = 0.f;
#pragma unroll
                    for (int ti = 0; ti < 2; ti++) {
#pragma unroll
                        for (int rh = 0; rh < 2; rh++) {
                            int w = w0 + 16 * ti + lg + 8 * rh;
                            float v = acc[ti][nt][2 * rh + rk] + bk;
                            float y = v > 0.0f ? v : (__expf(v) - 1.0f);
                            if (w < whi) {
                                s1 += y;
                                s2 += y * y;
                                if (w < N_POOL * P_POOL) {
                                    float pv = y * 0.01f;
                                    if (w / P_POOL == p0) q0 += pv; else q1 += pv;
                                }
                            }
                        }
                    }
#pragma unroll
                    for (int off = 4; off < 32; off <<= 1) {
                        s1 += __shfl_xor_sync(0xffffffffu, s1, off);
                        s2 += __shfl_xor_sync(0xffffffffu, s2, off);
                        q0 += __shfl_xor_sync(0xffffffffu, q0, off);
                        q1 += __shfl_xor_sync(0xffffffffu, q1, off);
                    }
                    if (lg == 0) {
                        atomicAdd(&sb1[k], s1);
                        atomicAdd(&sb2[k], s2);
                        if (p0 < N_POOL)     atomicAdd(&spool[k * N_POOL + p0], q0);
                        if (p0 + 1 < N_POOL) atomicAdd(&spool[k * N_POOL + p0 + 1], q1);
                    }
                }
            }
        }
        __syncthreads();

        // write only this half's pool bins (disjoint across the two halves of b)
        float* gp = g_pooled + (size_t)b * FEAT;
        for (int i = tid; i < FEAT; i += NTHR) {
            int n = i - (i / N_POOL) * N_POOL;
            bool mine = half ? (n >= 5) : (n < 5);
            if (mine) gp[i] = spool[i];
        }
        if (tid < K_OUT) {
            g_bnpart[(size_t)bx * (2 * K_OUT) + tid]         = sb1[tid];
            g_bnpart[(size_t)bx * (2 * K_OUT) + K_OUT + tid] = sb2[tid];
        }
    }
}

// ---------------- pass 2: BN stats reduce (over 2B partials) ----------------
__global__ void bn_reduce_kernel(const float* __restrict__ gamma,
                                 const float* __restrict__ beta) {
    __shared__ float r1[256];
    __shared__ float r2[256];
    int k = blockIdx.x;
    int tid = threadIdx.x;
    float s1 = 0.0f, s2 = 0.0f;
    for (int bx = tid; bx < NITEM; bx += 256) {
        s1 += g_bnpart[(size_t)bx * (2 * K_OUT) + k];
        s2 += g_bnpart[(size_t)bx * (2 * K_OUT) + K_OUT + k];
    }
    r1[tid] = s1; r2[tid] = s2;
    __syncthreads();
    for (int s = 128; s > 0; s >>= 1) {
        if (tid < s) { r1[tid] += r1[tid + s]; r2[tid] += r2[tid + s]; }
        __syncthreads();
    }
    if (tid == 0) {
        const float N = (float)((size_t)B_SIZE * W_OUT);
        float mean = r1[0] / N;
        float var  = r2[0] / N - mean * mean;
        float sc   = gamma[k] * rsqrtf(var + 1e-5f);
        g_scale[k] = sc;
        g_shift[k] = beta[k] - mean * sc;
    }
}

// ---------------- pass 3: subject-gathered FC (warp per sample) ----------------
__global__ void fc_kernel(const float* __restrict__ x,
                          const float* __restrict__ fc_w,
                          const float* __restrict__ fc_b,
                          float* __restrict__ out) {
    int wid  = threadIdx.x >> 5;
    int lane = threadIdx.x & 31;
    int b = blockIdx.x * 8 + wid;
    if (b >= B_SIZE) return;
    int sid = __float2int_rn(x[(size_t)b * (C_CH * T_FULL) + T_IN] * 1e-6f) - 1;
    const float4* Wp = (const float4*)(fc_w + (size_t)sid * FEAT * O_OUT);
    const float*  pf = g_pooled + (size_t)b * FEAT;
    float a0 = 0.f, a1 = 0.f, a2 = 0.f, a3 = 0.f;
#pragma unroll
    for (int j = 0; j < 12; j++) {
        int f = lane + j * 32;
        if (f < FEAT) {
            int k = f / N_POOL;
            float v = pf[f] * g_scale[k] + g_shift[k];
            float4 wv = Wp[f];
            a0 += v * wv.x; a1 += v * wv.y; a2 += v * wv.z; a3 += v * wv.w;
        }
    }
#pragma unroll
    for (int off = 16; off > 0; off >>= 1) {
        a0 += __shfl_xor_sync(0xffffffffu, a0, off);
        a1 += __shfl_xor_sync(0xffffffffu, a1, off);
        a2 += __shfl_xor_sync(0xffffffffu, a2, off);
        a3 += __shfl_xor_sync(0xffffffffu, a3, off);
    }
    if (lane == 0) {
        const float* fb = fc_b + sid * O_OUT;
        float4 o = make_float4(a0 + fb[0], a1 + fb[1], a2 + fb[2], a3 + fb[3]);
        ((float4*)out)[b] = o;
    }
}

// ---------------- launch ----------------
extern "C" void kernel_launch(void* const* d_in, const int* in_sizes, int n_in,
                              void* d_out, int out_size) {
    const float* x      = (const float*)d_in[0];
    const float* conv_w = (const float*)d_in[1];
    const float* conv_b = (const float*)d_in[2];
    const float* gamma  = (const float*)d_in[3];
    const float* beta   = (const float*)d_in[4];
    const float* fc_w   = (const float*)d_in[5];
    const float* fc_b   = (const float*)d_in[6];
    float* out = (float*)d_out;

    cudaFuncSetAttribute(conv_mma_kernel,
                         cudaFuncAttributeMaxDynamicSharedMemorySize, SMEM_BYTES);

    prep_w_kernel<<<(SWH2 + 255) / 256, 256>>>(conv_w);
    conv_mma_kernel<<<NCTA, NTHR, SMEM_BYTES>>>(x, conv_b);
    bn_reduce_kernel<<<K_OUT, 256>>>(gamma, beta);
    fc_kernel<<<B_SIZE / 8, 256>>>(x, fc_w, fc_b, out);
}